// round 11
// baseline (speedup 1.0000x reference)
#include <cuda_runtime.h>
#include <cuda_bf16.h>
#include <math.h>
#include <stdint.h>

#define QN 4
#define DD 768
#define NN 1024
#define HH 512
#define MM 8192
#define DD2 1536

// ---------------- device scratch (no runtime allocation) -------------------
__device__ float g_res[MM*DD];
__device__ __align__(128) __nv_bfloat16 g_Ahi[MM*DD];
__device__ __align__(128) __nv_bfloat16 g_Alo[MM*DD];
__device__ __align__(128) __nv_bfloat16 g_Hhi[MM*DD2];
__device__ __align__(128) __nv_bfloat16 g_Hlo[MM*DD2];
#define WT_TOTAL 6029312
__device__ __align__(128) __nv_bfloat16 g_Wthi[WT_TOTAL];
__device__ __align__(128) __nv_bfloat16 g_Wtlo[WT_TOTAL];

// weight-split layout (elements)
#define O_P1 0
#define SZ_P1 393216            /* 512*768  */
#define O_P2 1572864
#define SZ_P2 524288            /* 1024*512 */
#define O_D1 3670016
#define O_D2 4849664

// ---------------- PTX helpers ----------------------------------------------
__device__ __forceinline__ uint32_t smem_u32(const void* p) {
    uint32_t a;
    asm("{ .reg .u64 t; cvta.to.shared.u64 t, %1; cvt.u32.u64 %0, t; }" : "=r"(a) : "l"(p));
    return a;
}
#define CP_ASYNC16(dst, src) \
    asm volatile("cp.async.cg.shared.global [%0], [%1], 16;\n" :: "r"(dst), "l"(src))
#define CP_COMMIT() asm volatile("cp.async.commit_group;\n" ::: "memory")
#define CP_WAIT(n)  asm volatile("cp.async.wait_group %0;\n" :: "n"(n) : "memory")

#define LDSM4(f, addr) \
    asm volatile("ldmatrix.sync.aligned.m8n8.x4.shared.b16 {%0,%1,%2,%3}, [%4];\n" \
        : "=r"((f)[0]), "=r"((f)[1]), "=r"((f)[2]), "=r"((f)[3]) : "r"(addr))

#define MMA16816(d, a, b0, b1) \
    asm volatile("mma.sync.aligned.m16n8k16.row.col.f32.bf16.bf16.f32 " \
        "{%0,%1,%2,%3}, {%4,%5,%6,%7}, {%8,%9}, {%0,%1,%2,%3};\n" \
        : "+f"((d)[0]), "+f"((d)[1]), "+f"((d)[2]), "+f"((d)[3]) \
        : "r"((a)[0]), "r"((a)[1]), "r"((a)[2]), "r"((a)[3]), "r"(b0), "r"(b1))

// ---------------- small kernels --------------------------------------------
__global__ void init_kernel(const float* __restrict__ x) {
    int i = blockIdx.x * blockDim.x + threadIdx.x;
    if (i >= MM*DD/4) return;
    float4 a = ((const float4*)x)[i];
    ((float4*)g_res)[i] = a;
    float av[4] = {a.x, a.y, a.z, a.w};
    __nv_bfloat16 h[4], l[4];
#pragma unroll
    for (int j = 0; j < 4; j++) {
        h[j] = __float2bfloat16(av[j]);
        l[j] = __float2bfloat16(av[j] - __bfloat162float(h[j]));
    }
    ((ushort4*)g_Ahi)[i] = make_ushort4(*(unsigned short*)&h[0], *(unsigned short*)&h[1],
                                        *(unsigned short*)&h[2], *(unsigned short*)&h[3]);
    ((ushort4*)g_Alo)[i] = make_ushort4(*(unsigned short*)&l[0], *(unsigned short*)&l[1],
                                        *(unsigned short*)&l[2], *(unsigned short*)&l[3]);
}

// ALL weight transposes+splits in ONE launch (tile map as R8).
__global__ void wsplit_all(const float* __restrict__ pW1, const float* __restrict__ pW2,
                           const float* __restrict__ dW1, const float* __restrict__ dW2) {
    __shared__ float t[32][33];
    int tb = blockIdx.x;
    const float* W;
    int K, N;
    size_t dstoff;
    if (tb < 1536) {
        int i = tb / 384; tb -= i * 384;
        W = pW1 + (size_t)i * DD * HH; K = DD; N = HH; dstoff = O_P1 + (size_t)i * SZ_P1;
    } else if (tb < 3584) {
        int u = tb - 1536; int i = u / 512; tb = u - i * 512;
        W = pW2 + (size_t)i * HH * NN; K = HH; N = NN; dstoff = O_P2 + (size_t)i * SZ_P2;
    } else if (tb < 4736) {
        tb -= 3584; W = dW1; K = DD; N = DD2; dstoff = O_D1;
    } else {
        tb -= 4736; W = dW2; K = DD2; N = DD; dstoff = O_D2;
    }
    int ntx = N >> 5;
    int n0 = (tb % ntx) << 5, k0 = (tb / ntx) << 5;
    __nv_bfloat16* Thi = g_Wthi + dstoff;
    __nv_bfloat16* Tlo = g_Wtlo + dstoff;
    for (int i = threadIdx.y; i < 32; i += 8)
        t[i][threadIdx.x] = W[(size_t)(k0 + i) * N + n0 + threadIdx.x];
    __syncthreads();
    for (int i = threadIdx.y; i < 32; i += 8) {
        float val = t[threadIdx.x][i];
        __nv_bfloat16 h = __float2bfloat16(val);
        size_t o = (size_t)(n0 + i) * K + k0 + threadIdx.x;
        Thi[o] = h;
        Tlo[o] = __float2bfloat16(val - __bfloat162float(h));
    }
}

// -------- persistent mma.sync split-bf16 GEMM (R9 compute config) ----------
// C[M,Nc] = relu(bn(A @ W)). 128x128 tiles, BK=64, interleaved hi|lo 256B
// rows, 3-stage cp.async pipeline that NEVER drains across tiles: each CTA
// walks tiles bid, bid+NSM, ... with a flat chunk counter; during epilogue of
// tile t, chunks 0-1 of tile t+1 are already in flight. 256 thr, 8 warps
// (64x32), 1 CTA/SM. mode 0: fp32 out. mode 1: bf16 hi/lo split out.
#define GS_STAGE 65536            /* 32KB A(hi|lo) + 32KB W(hi|lo) */
#define SMEM_G   196608           /* 3 stages */

__global__ __launch_bounds__(256, 1)
void mma_gemm(const __nv_bfloat16* __restrict__ Ahi, const __nv_bfloat16* __restrict__ Alo,
              const __nv_bfloat16* __restrict__ Whi, const __nv_bfloat16* __restrict__ Wlo,
              const float* __restrict__ bb, const float* __restrict__ gg,
              const float* __restrict__ be, const float* __restrict__ mm_,
              const float* __restrict__ vv,
              float* __restrict__ Cf, __nv_bfloat16* __restrict__ Chi,
              __nv_bfloat16* __restrict__ Clo, int K, int Nc, int mode)
{
    extern __shared__ __align__(1024) char smem[];
    const uint32_t sbase = smem_u32(smem);
    const int tid = threadIdx.x;
    const int bid = blockIdx.x;
    const int NSM = gridDim.x;
    const int nx = Nc >> 7;
    const int ntiles = (MM >> 7) * nx;
    const int NC = K >> 6;

    const int lane = tid & 31, wid = tid >> 5;
    const int wm = (wid >> 2) << 6;     // 0 or 64
    const int wn = (wid & 3) << 5;      // 0,32,64,96

    // ldmatrix address precompute (row stride 256B)
    uint32_t aoff[4]; int asw[4];
#pragma unroll
    for (int im = 0; im < 4; im++) {
        int r = wm + (im << 4) + (lane & 15);
        aoff[im] = (uint32_t)(r << 8);
        asw[im] = r & 7;
    }
    const int acb = lane >> 4;
    uint32_t boff[2]; int bsw[2];
#pragma unroll
    for (int jn = 0; jn < 2; jn++) {
        int r = wn + (jn << 4) + (lane & 7) + (((lane >> 4) & 1) << 3);
        boff[jn] = (uint32_t)(r << 8);
        bsw[jn] = r & 7;
    }
    const int bcb = (lane >> 3) & 1;

    // loader thread mapping
    const int lrow0 = tid >> 4;          // 0..15
    const int lc16  = tid & 15;
    const int lhalf = lc16 >> 3;         // 0=hi, 1=lo
    const int lcc   = lc16 & 7;
    const __nv_bfloat16* Asrc = lhalf ? Alo : Ahi;
    const __nv_bfloat16* Wsrc = lhalf ? Wlo : Whi;
    const uint32_t lhoff = (uint32_t)(lhalf << 7);

    // prefetch state (flat chunk pipeline across tiles)
    int pf_tile = bid, pf_k = 0, pf_stage = 0;
    auto load_pf = [&]() {
        if (pf_tile < ntiles) {
            int ty = pf_tile / nx;
            int pm0 = ty << 7;
            int pn0 = (pf_tile - ty * nx) << 7;
            int k0 = pf_k << 6;
            uint32_t bA = sbase + pf_stage * GS_STAGE;
            uint32_t bB = bA + 32768;
#pragma unroll
            for (int j = 0; j < 8; j++) {
                int row = lrow0 + (j << 4);
                uint32_t sw = (uint32_t)(row << 8) + lhoff + (uint32_t)((lcc ^ (row & 7)) << 4);
                CP_ASYNC16(bA + sw, Asrc + (size_t)(pm0 + row) * K + k0 + (lcc << 3));
                CP_ASYNC16(bB + sw, Wsrc + (size_t)(pn0 + row) * K + k0 + (lcc << 3));
            }
        }
        CP_COMMIT();
        pf_stage = (pf_stage == 2) ? 0 : pf_stage + 1;
        if (++pf_k == NC) { pf_k = 0; pf_tile += NSM; }
    };

    load_pf();
    load_pf();

    int cs = 0;                          // compute stage (flat%3, continuous)
    for (int tile = bid; tile < ntiles; tile += NSM) {
        int ty = tile / nx;
        int m0 = ty << 7;
        int n0 = (tile - ty * nx) << 7;

        float acc[4][4][4];
#pragma unroll
        for (int im = 0; im < 4; im++)
#pragma unroll
            for (int in = 0; in < 4; in++)
#pragma unroll
                for (int r = 0; r < 4; r++) acc[im][in][r] = 0.f;

        for (int c = 0; c < NC; c++) {
            CP_WAIT(1);
            __syncthreads();
            load_pf();

            uint32_t sA = sbase + cs * GS_STAGE;
            uint32_t sB = sA + 32768;
            cs = (cs == 2) ? 0 : cs + 1;
#pragma unroll
            for (int kk = 0; kk < 4; kk++) {
                uint32_t afh[4][4], afl[4][4], bfh[2][4], bfl[2][4];
                const int sela = (kk << 1) + acb;
                const int selb = (kk << 1) + bcb;
#pragma unroll
                for (int im = 0; im < 4; im++) {
                    uint32_t base = sA + aoff[im] + (uint32_t)((sela ^ asw[im]) << 4);
                    LDSM4(afh[im], base);
                    LDSM4(afl[im], base + 128);
                }
#pragma unroll
                for (int jn = 0; jn < 2; jn++) {
                    uint32_t base = sB + boff[jn] + (uint32_t)((selb ^ bsw[jn]) << 4);
                    LDSM4(bfh[jn], base);
                    LDSM4(bfl[jn], base + 128);
                }
                // hh
#pragma unroll
                for (int im = 0; im < 4; im++)
#pragma unroll
                    for (int in = 0; in < 4; in++) {
                        const uint32_t* bp = bfh[in >> 1];
                        if (in & 1) MMA16816(acc[im][in], afh[im], bp[2], bp[3]);
                        else        MMA16816(acc[im][in], afh[im], bp[0], bp[1]);
                    }
                // hi * lo
#pragma unroll
                for (int im = 0; im < 4; im++)
#pragma unroll
                    for (int in = 0; in < 4; in++) {
                        const uint32_t* bp = bfl[in >> 1];
                        if (in & 1) MMA16816(acc[im][in], afh[im], bp[2], bp[3]);
                        else        MMA16816(acc[im][in], afh[im], bp[0], bp[1]);
                    }
                // lo * hi
#pragma unroll
                for (int im = 0; im < 4; im++)
#pragma unroll
                    for (int in = 0; in < 4; in++) {
                        const uint32_t* bp = bfh[in >> 1];
                        if (in & 1) MMA16816(acc[im][in], afl[im], bp[2], bp[3]);
                        else        MMA16816(acc[im][in], afl[im], bp[0], bp[1]);
                    }
            }
        }

        // ---- epilogue: BN + ReLU (params read direct, L1-hot) --------------
        const int rbase = m0 + wm + (lane >> 2);
        const int clbase = wn + ((lane & 3) << 1);
#pragma unroll
        for (int in = 0; in < 4; in++) {
            int cl = clbase + (in << 3);
            int gc = n0 + cl;
            float s0 = gg[gc] * rsqrtf(vv[gc] + 1e-5f);
            float o0 = (bb[gc] - mm_[gc]) * s0 + be[gc];
            float s1 = gg[gc+1] * rsqrtf(vv[gc+1] + 1e-5f);
            float o1 = (bb[gc+1] - mm_[gc+1]) * s1 + be[gc+1];
#pragma unroll
            for (int im = 0; im < 4; im++) {
                int row = rbase + (im << 4);
                float v0 = fmaxf(acc[im][in][0] * s0 + o0, 0.f);
                float v1 = fmaxf(acc[im][in][1] * s1 + o1, 0.f);
                float v2 = fmaxf(acc[im][in][2] * s0 + o0, 0.f);
                float v3 = fmaxf(acc[im][in][3] * s1 + o1, 0.f);
                size_t p0 = (size_t)row * Nc + gc;
                size_t p1 = (size_t)(row + 8) * Nc + gc;
                if (mode == 0) {
                    float2 w0; w0.x = v0; w0.y = v1;
                    float2 w1; w1.x = v2; w1.y = v3;
                    *(float2*)&Cf[p0] = w0;
                    *(float2*)&Cf[p1] = w1;
                } else {
                    __nv_bfloat16 h0 = __float2bfloat16(v0);
                    __nv_bfloat16 h1 = __float2bfloat16(v1);
                    __nv_bfloat16 h2 = __float2bfloat16(v2);
                    __nv_bfloat16 h3 = __float2bfloat16(v3);
                    __nv_bfloat162 hp0; hp0.x = h0; hp0.y = h1;
                    __nv_bfloat162 hp1; hp1.x = h2; hp1.y = h3;
                    __nv_bfloat162 lp0, lp1;
                    lp0.x = __float2bfloat16(v0 - __bfloat162float(h0));
                    lp0.y = __float2bfloat16(v1 - __bfloat162float(h1));
                    lp1.x = __float2bfloat16(v2 - __bfloat162float(h2));
                    lp1.y = __float2bfloat16(v3 - __bfloat162float(h3));
                    *(__nv_bfloat162*)&Chi[p0] = hp0;
                    *(__nv_bfloat162*)&Chi[p1] = hp1;
                    *(__nv_bfloat162*)&Clo[p0] = lp0;
                    *(__nv_bfloat162*)&Clo[p1] = lp1;
                }
            }
        }
    }
}

// ---------------- token kernel (float4, unchanged from R8) -------------------
__global__ void token_kernel(const float* __restrict__ z,
                             const float* __restrict__ gum,
                             const float* __restrict__ cb,
                             const float* __restrict__ x,
                             float* __restrict__ ent_out,
                             float* __restrict__ lat_out,
                             float* __restrict__ idx_out,
                             int split_mode)
{
    const int t = blockIdx.x;
    const int tid = threadIdx.x;
    const int lane = tid & 31, wrp = tid >> 5;

    __shared__ float swa[8];
    __shared__ float swb[8];
    __shared__ int   swi[8];

    float4 z4 = ((const float4*)(z + (size_t)t * NN))[tid];
    float4 g4 = ((const float4*)(gum + (size_t)t * NN))[tid];
    float zv[4] = {z4.x, z4.y, z4.z, z4.w};
    float gv[4] = {g4.x, g4.y, g4.z, g4.w};

    float lmax = -INFINITY;
    float amax = -INFINITY;
    int   aidx = 0x7fffffff;
#pragma unroll
    for (int k = 0; k < 4; k++) {
        lmax = fmaxf(lmax, zv[k]);
        float lg = zv[k] + gv[k];
        if (lg > amax) { amax = lg; aidx = (tid << 2) + k; }
    }
#pragma unroll
    for (int o = 16; o > 0; o >>= 1) {
        lmax = fmaxf(lmax, __shfl_xor_sync(0xffffffffu, lmax, o));
        float ov = __shfl_xor_sync(0xffffffffu, amax, o);
        int   oi = __shfl_xor_sync(0xffffffffu, aidx, o);
        if (ov > amax || (ov == amax && oi < aidx)) { amax = ov; aidx = oi; }
    }
    if (lane == 0) { swa[wrp] = lmax; swb[wrp] = amax; swi[wrp] = aidx; }
    __syncthreads();
    float zmax = swa[0];
    float bv = swb[0]; int bi = swi[0];
#pragma unroll
    for (int w = 1; w < 8; w++) {
        zmax = fmaxf(zmax, swa[w]);
        float ov = swb[w]; int oi = swi[w];
        if (ov > bv || (ov == bv && oi < bi)) { bv = ov; bi = oi; }
    }
    const int idx = bi;
    __syncthreads();

    float ex[4];
    float se = 0.f;
#pragma unroll
    for (int k = 0; k < 4; k++) { ex[k] = expf(zv[k] - zmax); se += ex[k]; }
#pragma unroll
    for (int o = 16; o > 0; o >>= 1) se += __shfl_xor_sync(0xffffffffu, se, o);
    if (lane == 0) swa[wrp] = se;
    __syncthreads();
    float tot = 0.f;
#pragma unroll
    for (int w = 0; w < 8; w++) tot += swa[w];
    const float inv = 1.f / tot;

    float entp = 0.f;
    float lt[4];
#pragma unroll
    for (int k = 0; k < 4; k++) {
        float qy = ex[k] * inv;
        entp -= qy * logf(qy + 1e-10f);
        lt[k] = qy * logf(qy * 1024.f + 1e-10f);
    }
    float4 l4; l4.x = lt[0]; l4.y = lt[1]; l4.z = lt[2]; l4.w = lt[3];
    ((float4*)(lat_out + (size_t)t * NN))[tid] = l4;
#pragma unroll
    for (int o = 16; o > 0; o >>= 1) entp += __shfl_xor_sync(0xffffffffu, entp, o);
    __syncthreads();
    if (lane == 0) swb[wrp] = entp;
    __syncthreads();
    if (tid == 0) {
        float e = 0.f;
#pragma unroll
        for (int w = 0; w < 8; w++) e += swb[w];
        ent_out[t] = e;
        idx_out[t] = (float)idx;
    }

    if (tid < DD/4) {
        const float4* cb4 = (const float4*)(cb + (size_t)idx * DD);
        float4* rr4 = (float4*)(g_res + (size_t)t * DD);
        float4 c4 = cb4[tid];
        float4 r4 = rr4[tid];
        r4.x -= c4.x; r4.y -= c4.y; r4.z -= c4.z; r4.w -= c4.w;
        float sv[4];
        if (split_mode) {
            float4 x4 = ((const float4*)(x + (size_t)t * DD))[tid];
            sv[0] = x4.x - r4.x; sv[1] = x4.y - r4.y;
            sv[2] = x4.z - r4.z; sv[3] = x4.w - r4.w;
        } else {
            rr4[tid] = r4;
            sv[0] = r4.x; sv[1] = r4.y; sv[2] = r4.z; sv[3] = r4.w;
        }
        __nv_bfloat16 h[4], l[4];
#pragma unroll
        for (int k = 0; k < 4; k++) {
            h[k] = __float2bfloat16(sv[k]);
            l[k] = __float2bfloat16(sv[k] - __bfloat162float(h[k]));
        }
        ((ushort4*)(g_Ahi + (size_t)t * DD))[tid] =
            make_ushort4(*(unsigned short*)&h[0], *(unsigned short*)&h[1],
                         *(unsigned short*)&h[2], *(unsigned short*)&h[3]);
        ((ushort4*)(g_Alo + (size_t)t * DD))[tid] =
            make_ushort4(*(unsigned short*)&l[0], *(unsigned short*)&l[1],
                         *(unsigned short*)&l[2], *(unsigned short*)&l[3]);
    }
}

// ---------------- host launch ----------------------------------------------
extern "C" void kernel_launch(void* const* d_in, const int* in_sizes, int n_in,
                              void* d_out, int out_size)
{
    const float* x    = (const float*)d_in[0];
    const float* cb   = (const float*)d_in[1];
    const float* pW1  = (const float*)d_in[2];
    const float* pb1  = (const float*)d_in[3];
    const float* pg1  = (const float*)d_in[4];
    const float* pbe1 = (const float*)d_in[5];
    const float* pm1  = (const float*)d_in[6];
    const float* pv1  = (const float*)d_in[7];
    const float* pW2  = (const float*)d_in[8];
    const float* pb2  = (const float*)d_in[9];
    const float* pg2  = (const float*)d_in[10];
    const float* pbe2 = (const float*)d_in[11];
    const float* pm2  = (const float*)d_in[12];
    const float* pv2  = (const float*)d_in[13];
    const float* dW1  = (const float*)d_in[14];
    const float* db1  = (const float*)d_in[15];
    const float* dg1  = (const float*)d_in[16];
    const float* dbe1 = (const float*)d_in[17];
    const float* dm1  = (const float*)d_in[18];
    const float* dv1  = (const float*)d_in[19];
    const float* dW2  = (const float*)d_in[20];
    const float* db2  = (const float*)d_in[21];
    const float* dg2  = (const float*)d_in[22];
    const float* dbe2 = (const float*)d_in[23];
    const float* dm2  = (const float*)d_in[24];
    const float* dv2  = (const float*)d_in[25];
    const float* gum  = (const float*)d_in[26];

    float* out  = (float*)d_out;
    float* xhat = out;                                  // [MM, DD]
    float* ent  = xhat + (size_t)MM * DD;               // [QN, MM]
    float* lat  = ent  + (size_t)QN * MM;               // [QN, MM, NN]
    float* idxo = lat  + (size_t)QN * MM * NN;          // [QN, MM]
    float* zs   = idxo + (size_t)QN * MM;               // [QN, MM, NN]

    __nv_bfloat16 *Ahi, *Alo, *Hhi, *Hlo, *Wthi, *Wtlo;
    cudaGetSymbolAddress((void**)&Ahi,  g_Ahi);
    cudaGetSymbolAddress((void**)&Alo,  g_Alo);
    cudaGetSymbolAddress((void**)&Hhi,  g_Hhi);
    cudaGetSymbolAddress((void**)&Hlo,  g_Hlo);
    cudaGetSymbolAddress((void**)&Wthi, g_Wthi);
    cudaGetSymbolAddress((void**)&Wtlo, g_Wtlo);

    int nsm = 148;
    cudaDeviceGetAttribute(&nsm, cudaDevAttrMultiProcessorCount, 0);

    cudaFuncSetAttribute(mma_gemm, cudaFuncAttributeMaxDynamicSharedMemorySize, SMEM_G);

    init_kernel<<<(MM*DD/4 + 255) / 256, 256>>>(x);
    wsplit_all<<<5888, dim3(32, 8)>>>(pW1, pW2, dW1, dW2);

    for (int i = 0; i < QN; i++) {
        // h = blk(res @ pW1) -> bf16 split [8192 x 512]
        mma_gemm<<<nsm, 256, SMEM_G>>>(
            Ahi, Alo, Wthi + O_P1 + (size_t)i*SZ_P1, Wtlo + O_P1 + (size_t)i*SZ_P1,
            pb1 + i*HH, pg1 + i*HH, pbe1 + i*HH, pm1 + i*HH, pv1 + i*HH,
            nullptr, Hhi, Hlo, DD, HH, 1);
        // z = blk(h @ pW2) -> fp32 zs slice [8192 x 1024]
        float* z_i = zs + (size_t)i * MM * NN;
        mma_gemm<<<nsm, 256, SMEM_G>>>(
            Hhi, Hlo, Wthi + O_P2 + (size_t)i*SZ_P2, Wtlo + O_P2 + (size_t)i*SZ_P2,
            pb2 + i*NN, pg2 + i*NN, pbe2 + i*NN, pm2 + i*NN, pv2 + i*NN,
            z_i, nullptr, nullptr, HH, NN, 0);
        token_kernel<<<MM, 256>>>(
            z_i, gum + (size_t)i * MM * NN, cb + (size_t)i * NN * DD, x,
            ent + (size_t)i * MM, lat + (size_t)i * MM * NN, idxo + (size_t)i * MM,
            (i == QN - 1) ? 1 : 0);
    }

    // decoder (Ahi/Alo hold split(qout))
    mma_gemm<<<nsm, 256, SMEM_G>>>(
        Ahi, Alo, Wthi + O_D1, Wtlo + O_D1,
        db1, dg1, dbe1, dm1, dv1,
        nullptr, Hhi, Hlo, DD, DD2, 1);
    mma_gemm<<<nsm, 256, SMEM_G>>>(
        Hhi, Hlo, Wthi + O_D2, Wtlo + O_D2,
        db2, dg2, dbe2, dm2, dv2,
        xhat, nullptr, nullptr, DD2, DD, 0);
}

// round 12
// speedup vs baseline: 1.0471x; 1.0471x over previous
#include <cuda_runtime.h>
#include <cuda_bf16.h>
#include <math.h>
#include <stdint.h>

#define QN 4
#define DD 768
#define NN 1024
#define HH 512
#define MM 8192
#define DD2 1536

// ---------------- device scratch (no runtime allocation) -------------------
__device__ float g_res[MM*DD];
__device__ __align__(128) __nv_bfloat16 g_Ahi[MM*DD];
__device__ __align__(128) __nv_bfloat16 g_Alo[MM*DD];
__device__ __align__(128) __nv_bfloat16 g_Hhi[MM*DD2];
__device__ __align__(128) __nv_bfloat16 g_Hlo[MM*DD2];
#define WT_TOTAL 6029312
__device__ __align__(128) __nv_bfloat16 g_Wthi[WT_TOTAL];
__device__ __align__(128) __nv_bfloat16 g_Wtlo[WT_TOTAL];

// weight-split layout (elements)
#define O_P1 0
#define SZ_P1 393216            /* 512*768  */
#define O_P2 1572864
#define SZ_P2 524288            /* 1024*512 */
#define O_D1 3670016
#define O_D2 4849664

// ---------------- PTX helpers ----------------------------------------------
__device__ __forceinline__ uint32_t smem_u32(const void* p) {
    uint32_t a;
    asm("{ .reg .u64 t; cvta.to.shared.u64 t, %1; cvt.u32.u64 %0, t; }" : "=r"(a) : "l"(p));
    return a;
}
#define CP_ASYNC16(dst, src) \
    asm volatile("cp.async.cg.shared.global [%0], [%1], 16;\n" :: "r"(dst), "l"(src))
#define CP_COMMIT() asm volatile("cp.async.commit_group;\n" ::: "memory")
#define CP_WAIT(n)  asm volatile("cp.async.wait_group %0;\n" :: "n"(n) : "memory")

#define LDSM4(f, addr) \
    asm volatile("ldmatrix.sync.aligned.m8n8.x4.shared.b16 {%0,%1,%2,%3}, [%4];\n" \
        : "=r"((f)[0]), "=r"((f)[1]), "=r"((f)[2]), "=r"((f)[3]) : "r"(addr))

#define MMA16816(d, a, b0, b1) \
    asm volatile("mma.sync.aligned.m16n8k16.row.col.f32.bf16.bf16.f32 " \
        "{%0,%1,%2,%3}, {%4,%5,%6,%7}, {%8,%9}, {%0,%1,%2,%3};\n" \
        : "+f"((d)[0]), "+f"((d)[1]), "+f"((d)[2]), "+f"((d)[3]) \
        : "r"((a)[0]), "r"((a)[1]), "r"((a)[2]), "r"((a)[3]), "r"(b0), "r"(b1))

// ---------------- small kernels --------------------------------------------
__global__ void init_kernel(const float* __restrict__ x) {
    int i = blockIdx.x * blockDim.x + threadIdx.x;
    if (i >= MM*DD/4) return;
    float4 a = ((const float4*)x)[i];
    ((float4*)g_res)[i] = a;
    float av[4] = {a.x, a.y, a.z, a.w};
    __nv_bfloat16 h[4], l[4];
#pragma unroll
    for (int j = 0; j < 4; j++) {
        h[j] = __float2bfloat16(av[j]);
        l[j] = __float2bfloat16(av[j] - __bfloat162float(h[j]));
    }
    ((ushort4*)g_Ahi)[i] = make_ushort4(*(unsigned short*)&h[0], *(unsigned short*)&h[1],
                                        *(unsigned short*)&h[2], *(unsigned short*)&h[3]);
    ((ushort4*)g_Alo)[i] = make_ushort4(*(unsigned short*)&l[0], *(unsigned short*)&l[1],
                                        *(unsigned short*)&l[2], *(unsigned short*)&l[3]);
}

// ALL weight transposes+splits in ONE launch (tile map as R8).
__global__ void wsplit_all(const float* __restrict__ pW1, const float* __restrict__ pW2,
                           const float* __restrict__ dW1, const float* __restrict__ dW2) {
    __shared__ float t[32][33];
    int tb = blockIdx.x;
    const float* W;
    int K, N;
    size_t dstoff;
    if (tb < 1536) {
        int i = tb / 384; tb -= i * 384;
        W = pW1 + (size_t)i * DD * HH; K = DD; N = HH; dstoff = O_P1 + (size_t)i * SZ_P1;
    } else if (tb < 3584) {
        int u = tb - 1536; int i = u / 512; tb = u - i * 512;
        W = pW2 + (size_t)i * HH * NN; K = HH; N = NN; dstoff = O_P2 + (size_t)i * SZ_P2;
    } else if (tb < 4736) {
        tb -= 3584; W = dW1; K = DD; N = DD2; dstoff = O_D1;
    } else {
        tb -= 4736; W = dW2; K = DD2; N = DD; dstoff = O_D2;
    }
    int ntx = N >> 5;
    int n0 = (tb % ntx) << 5, k0 = (tb / ntx) << 5;
    __nv_bfloat16* Thi = g_Wthi + dstoff;
    __nv_bfloat16* Tlo = g_Wtlo + dstoff;
    for (int i = threadIdx.y; i < 32; i += 8)
        t[i][threadIdx.x] = W[(size_t)(k0 + i) * N + n0 + threadIdx.x];
    __syncthreads();
    for (int i = threadIdx.y; i < 32; i += 8) {
        float val = t[threadIdx.x][i];
        __nv_bfloat16 h = __float2bfloat16(val);
        size_t o = (size_t)(n0 + i) * K + k0 + threadIdx.x;
        Thi[o] = h;
        Tlo[o] = __float2bfloat16(val - __bfloat162float(h));
    }
}

// ---- mma.sync split-bf16 GEMM (R9 base + kk-stagger + frag double-buffer) --
// C[M,Nc] = relu(bn(A @ W)). 128x128 CTA tile, BK=64, interleaved hi|lo 256B
// rows, 3-stage cp.async, one __syncthreads per chunk. 8 warps x (64x32).
// Warp row-group 1 processes kk in order 2,3,0,1 (anti-phase vs group 0), and
// kk+1 fragments are prefetched during kk's MMAs.
#define GS_STAGE 65536            /* 32KB A(hi|lo) + 32KB W(hi|lo) */
#define GS_SC    196608
#define SMEM_G   (196608 + 1024)

__global__ __launch_bounds__(256, 1)
void mma_gemm(const __nv_bfloat16* __restrict__ Ahi, const __nv_bfloat16* __restrict__ Alo,
              const __nv_bfloat16* __restrict__ Whi, const __nv_bfloat16* __restrict__ Wlo,
              const float* __restrict__ bb, const float* __restrict__ gg,
              const float* __restrict__ be, const float* __restrict__ mm_,
              const float* __restrict__ vv,
              float* __restrict__ Cf, __nv_bfloat16* __restrict__ Chi,
              __nv_bfloat16* __restrict__ Clo, int K, int mode)
{
    extern __shared__ __align__(1024) char smem[];
    const uint32_t sbase = smem_u32(smem);
    float* scp = (float*)(smem + GS_SC);
    float* ofp = scp + 128;
    const int tid = threadIdx.x;
    const int Nc = gridDim.x * 128;
    const int n0 = blockIdx.x * 128;
    const int m0 = blockIdx.y * 128;

    if (tid < 128) {
        int c = n0 + tid;
        float s = gg[c] * rsqrtf(vv[c] + 1e-5f);
        scp[tid] = s;
        ofp[tid] = (bb[c] - mm_[c]) * s + be[c];
    }

    const int lane = tid & 31, wid = tid >> 5;
    const int wm = (wid >> 2) << 6;     // 0 or 64
    const int wn = (wid & 3) << 5;      // 0,32,64,96
    const int kst = (wid >> 2) << 1;    // kk stagger: 0 or 2

    float acc[4][4][4];
#pragma unroll
    for (int im = 0; im < 4; im++)
#pragma unroll
        for (int in = 0; in < 4; in++)
#pragma unroll
            for (int r = 0; r < 4; r++) acc[im][in][r] = 0.f;

    // ldmatrix address precompute (row stride 256B)
    uint32_t aoff[4]; int asw[4];
#pragma unroll
    for (int im = 0; im < 4; im++) {
        int r = wm + (im << 4) + (lane & 15);
        aoff[im] = (uint32_t)(r << 8);
        asw[im] = r & 7;
    }
    const int acb = lane >> 4;
    uint32_t boff[2]; int bsw[2];
#pragma unroll
    for (int jn = 0; jn < 2; jn++) {
        int r = wn + (jn << 4) + (lane & 7) + (((lane >> 4) & 1) << 3);
        boff[jn] = (uint32_t)(r << 8);
        bsw[jn] = r & 7;
    }
    const int bcb = (lane >> 3) & 1;

    const int NC = K >> 6;

    // loader: per thread, 16B chunk index constant (tid&15): half = hi/lo select
    const int lrow0 = tid >> 4;          // 0..15
    const int lc16  = tid & 15;
    const int lhalf = lc16 >> 3;         // 0=hi, 1=lo
    const int lcc   = lc16 & 7;
    const __nv_bfloat16* Asrc = lhalf ? Alo : Ahi;
    const __nv_bfloat16* Wsrc = lhalf ? Wlo : Whi;
    const uint32_t lhoff = (uint32_t)(lhalf << 7);

    auto load_chunk = [&](int c, int s) {
        int k0 = c << 6;
        uint32_t bA = sbase + s * GS_STAGE;
        uint32_t bB = bA + 32768;
#pragma unroll
        for (int j = 0; j < 8; j++) {
            int row = lrow0 + (j << 4);
            uint32_t sw = (uint32_t)(row << 8) + lhoff + (uint32_t)((lcc ^ (row & 7)) << 4);
            CP_ASYNC16(bA + sw, Asrc + (size_t)(m0 + row) * K + k0 + (lcc << 3));
            CP_ASYNC16(bB + sw, Wsrc + (size_t)(n0 + row) * K + k0 + (lcc << 3));
        }
    };

    load_chunk(0, 0); CP_COMMIT();
    load_chunk(1, 1); CP_COMMIT();

    // double-buffered fragments
    uint32_t afh[2][4][4], afl[2][4][4], bfh[2][2][4], bfl[2][2][4];

    for (int c = 0; c < NC; c++) {
        CP_WAIT(1);
        __syncthreads();
        if (c + 2 < NC) load_chunk(c + 2, (c + 2) % 3);
        CP_COMMIT();

        uint32_t sA = sbase + (c % 3) * GS_STAGE;
        uint32_t sB = sA + 32768;

        // load fragments for first (staggered) kk into buffer 0
        {
            const int kr = kst;                   // kk_real
            const int sela = (kr << 1) + acb;
            const int selb = (kr << 1) + bcb;
#pragma unroll
            for (int im = 0; im < 4; im++) {
                uint32_t base = sA + aoff[im] + (uint32_t)((sela ^ asw[im]) << 4);
                LDSM4(afh[0][im], base);
                LDSM4(afl[0][im], base + 128);
            }
#pragma unroll
            for (int jn = 0; jn < 2; jn++) {
                uint32_t base = sB + boff[jn] + (uint32_t)((selb ^ bsw[jn]) << 4);
                LDSM4(bfh[0][jn], base);
                LDSM4(bfl[0][jn], base + 128);
            }
        }

#pragma unroll
        for (int kk = 0; kk < 4; kk++) {
            const int cur = kk & 1;
            const int nxt = cur ^ 1;
            if (kk < 3) {
                const int kr = (kk + 1 + kst) & 3;
                const int sela = (kr << 1) + acb;
                const int selb = (kr << 1) + bcb;
#pragma unroll
                for (int im = 0; im < 4; im++) {
                    uint32_t base = sA + aoff[im] + (uint32_t)((sela ^ asw[im]) << 4);
                    LDSM4(afh[nxt][im], base);
                    LDSM4(afl[nxt][im], base + 128);
                }
#pragma unroll
                for (int jn = 0; jn < 2; jn++) {
                    uint32_t base = sB + boff[jn] + (uint32_t)((selb ^ bsw[jn]) << 4);
                    LDSM4(bfh[nxt][jn], base);
                    LDSM4(bfl[nxt][jn], base + 128);
                }
            }
            // hh
#pragma unroll
            for (int im = 0; im < 4; im++)
#pragma unroll
                for (int in = 0; in < 4; in++) {
                    const uint32_t* bp = bfh[cur][in >> 1];
                    if (in & 1) MMA16816(acc[im][in], afh[cur][im], bp[2], bp[3]);
                    else        MMA16816(acc[im][in], afh[cur][im], bp[0], bp[1]);
                }
            // hi * lo
#pragma unroll
            for (int im = 0; im < 4; im++)
#pragma unroll
                for (int in = 0; in < 4; in++) {
                    const uint32_t* bp = bfl[cur][in >> 1];
                    if (in & 1) MMA16816(acc[im][in], afh[cur][im], bp[2], bp[3]);
                    else        MMA16816(acc[im][in], afh[cur][im], bp[0], bp[1]);
                }
            // lo * hi
#pragma unroll
            for (int im = 0; im < 4; im++)
#pragma unroll
                for (int in = 0; in < 4; in++) {
                    const uint32_t* bp = bfh[cur][in >> 1];
                    if (in & 1) MMA16816(acc[im][in], afl[cur][im], bp[2], bp[3]);
                    else        MMA16816(acc[im][in], afl[cur][im], bp[0], bp[1]);
                }
        }
    }

    // ---- epilogue: BN + ReLU ------------------------------------------------
    const int rbase = m0 + wm + (lane >> 2);
    const int clbase = wn + ((lane & 3) << 1);
#pragma unroll
    for (int im = 0; im < 4; im++) {
#pragma unroll
        for (int in = 0; in < 4; in++) {
            int row = rbase + (im << 4);
            int cl = clbase + (in << 3);
            float s0 = scp[cl], s1 = scp[cl + 1];
            float o0 = ofp[cl], o1 = ofp[cl + 1];
            float v0 = fmaxf(acc[im][in][0] * s0 + o0, 0.f);
            float v1 = fmaxf(acc[im][in][1] * s1 + o1, 0.f);
            float v2 = fmaxf(acc[im][in][2] * s0 + o0, 0.f);
            float v3 = fmaxf(acc[im][in][3] * s1 + o1, 0.f);
            size_t p0 = (size_t)row * Nc + n0 + cl;
            size_t p1 = (size_t)(row + 8) * Nc + n0 + cl;
            if (mode == 0) {
                float2 w0; w0.x = v0; w0.y = v1;
                float2 w1; w1.x = v2; w1.y = v3;
                *(float2*)&Cf[p0] = w0;
                *(float2*)&Cf[p1] = w1;
            } else {
                __nv_bfloat16 h0 = __float2bfloat16(v0);
                __nv_bfloat16 h1 = __float2bfloat16(v1);
                __nv_bfloat16 h2 = __float2bfloat16(v2);
                __nv_bfloat16 h3 = __float2bfloat16(v3);
                __nv_bfloat162 hp0; hp0.x = h0; hp0.y = h1;
                __nv_bfloat162 hp1; hp1.x = h2; hp1.y = h3;
                __nv_bfloat162 lp0, lp1;
                lp0.x = __float2bfloat16(v0 - __bfloat162float(h0));
                lp0.y = __float2bfloat16(v1 - __bfloat162float(h1));
                lp1.x = __float2bfloat16(v2 - __bfloat162float(h2));
                lp1.y = __float2bfloat16(v3 - __bfloat162float(h3));
                *(__nv_bfloat162*)&Chi[p0] = hp0;
                *(__nv_bfloat162*)&Chi[p1] = hp1;
                *(__nv_bfloat162*)&Clo[p0] = lp0;
                *(__nv_bfloat162*)&Clo[p1] = lp1;
            }
        }
    }
}

// ---------------- token kernel (float4, unchanged from R8) -------------------
__global__ void token_kernel(const float* __restrict__ z,
                             const float* __restrict__ gum,
                             const float* __restrict__ cb,
                             const float* __restrict__ x,
                             float* __restrict__ ent_out,
                             float* __restrict__ lat_out,
                             float* __restrict__ idx_out,
                             int split_mode)
{
    const int t = blockIdx.x;
    const int tid = threadIdx.x;
    const int lane = tid & 31, wrp = tid >> 5;

    __shared__ float swa[8];
    __shared__ float swb[8];
    __shared__ int   swi[8];

    float4 z4 = ((const float4*)(z + (size_t)t * NN))[tid];
    float4 g4 = ((const float4*)(gum + (size_t)t * NN))[tid];
    float zv[4] = {z4.x, z4.y, z4.z, z4.w};
    float gv[4] = {g4.x, g4.y, g4.z, g4.w};

    float lmax = -INFINITY;
    float amax = -INFINITY;
    int   aidx = 0x7fffffff;
#pragma unroll
    for (int k = 0; k < 4; k++) {
        lmax = fmaxf(lmax, zv[k]);
        float lg = zv[k] + gv[k];
        if (lg > amax) { amax = lg; aidx = (tid << 2) + k; }
    }
#pragma unroll
    for (int o = 16; o > 0; o >>= 1) {
        lmax = fmaxf(lmax, __shfl_xor_sync(0xffffffffu, lmax, o));
        float ov = __shfl_xor_sync(0xffffffffu, amax, o);
        int   oi = __shfl_xor_sync(0xffffffffu, aidx, o);
        if (ov > amax || (ov == amax && oi < aidx)) { amax = ov; aidx = oi; }
    }
    if (lane == 0) { swa[wrp] = lmax; swb[wrp] = amax; swi[wrp] = aidx; }
    __syncthreads();
    float zmax = swa[0];
    float bv = swb[0]; int bi = swi[0];
#pragma unroll
    for (int w = 1; w < 8; w++) {
        zmax = fmaxf(zmax, swa[w]);
        float ov = swb[w]; int oi = swi[w];
        if (ov > bv || (ov == bv && oi < bi)) { bv = ov; bi = oi; }
    }
    const int idx = bi;
    __syncthreads();

    float ex[4];
    float se = 0.f;
#pragma unroll
    for (int k = 0; k < 4; k++) { ex[k] = expf(zv[k] - zmax); se += ex[k]; }
#pragma unroll
    for (int o = 16; o > 0; o >>= 1) se += __shfl_xor_sync(0xffffffffu, se, o);
    if (lane == 0) swa[wrp] = se;
    __syncthreads();
    float tot = 0.f;
#pragma unroll
    for (int w = 0; w < 8; w++) tot += swa[w];
    const float inv = 1.f / tot;

    float entp = 0.f;
    float lt[4];
#pragma unroll
    for (int k = 0; k < 4; k++) {
        float qy = ex[k] * inv;
        entp -= qy * logf(qy + 1e-10f);
        lt[k] = qy * logf(qy * 1024.f + 1e-10f);
    }
    float4 l4; l4.x = lt[0]; l4.y = lt[1]; l4.z = lt[2]; l4.w = lt[3];
    ((float4*)(lat_out + (size_t)t * NN))[tid] = l4;
#pragma unroll
    for (int o = 16; o > 0; o >>= 1) entp += __shfl_xor_sync(0xffffffffu, entp, o);
    __syncthreads();
    if (lane == 0) swb[wrp] = entp;
    __syncthreads();
    if (tid == 0) {
        float e = 0.f;
#pragma unroll
        for (int w = 0; w < 8; w++) e += swb[w];
        ent_out[t] = e;
        idx_out[t] = (float)idx;
    }

    if (tid < DD/4) {
        const float4* cb4 = (const float4*)(cb + (size_t)idx * DD);
        float4* rr4 = (float4*)(g_res + (size_t)t * DD);
        float4 c4 = cb4[tid];
        float4 r4 = rr4[tid];
        r4.x -= c4.x; r4.y -= c4.y; r4.z -= c4.z; r4.w -= c4.w;
        float sv[4];
        if (split_mode) {
            float4 x4 = ((const float4*)(x + (size_t)t * DD))[tid];
            sv[0] = x4.x - r4.x; sv[1] = x4.y - r4.y;
            sv[2] = x4.z - r4.z; sv[3] = x4.w - r4.w;
        } else {
            rr4[tid] = r4;
            sv[0] = r4.x; sv[1] = r4.y; sv[2] = r4.z; sv[3] = r4.w;
        }
        __nv_bfloat16 h[4], l[4];
#pragma unroll
        for (int k = 0; k < 4; k++) {
            h[k] = __float2bfloat16(sv[k]);
            l[k] = __float2bfloat16(sv[k] - __bfloat162float(h[k]));
        }
        ((ushort4*)(g_Ahi + (size_t)t * DD))[tid] =
            make_ushort4(*(unsigned short*)&h[0], *(unsigned short*)&h[1],
                         *(unsigned short*)&h[2], *(unsigned short*)&h[3]);
        ((ushort4*)(g_Alo + (size_t)t * DD))[tid] =
            make_ushort4(*(unsigned short*)&l[0], *(unsigned short*)&l[1],
                         *(unsigned short*)&l[2], *(unsigned short*)&l[3]);
    }
}

// ---------------- host launch ----------------------------------------------
extern "C" void kernel_launch(void* const* d_in, const int* in_sizes, int n_in,
                              void* d_out, int out_size)
{
    const float* x    = (const float*)d_in[0];
    const float* cb   = (const float*)d_in[1];
    const float* pW1  = (const float*)d_in[2];
    const float* pb1  = (const float*)d_in[3];
    const float* pg1  = (const float*)d_in[4];
    const float* pbe1 = (const float*)d_in[5];
    const float* pm1  = (const float*)d_in[6];
    const float* pv1  = (const float*)d_in[7];
    const float* pW2  = (const float*)d_in[8];
    const float* pb2  = (const float*)d_in[9];
    const float* pg2  = (const float*)d_in[10];
    const float* pbe2 = (const float*)d_in[11];
    const float* pm2  = (const float*)d_in[12];
    const float* pv2  = (const float*)d_in[13];
    const float* dW1  = (const float*)d_in[14];
    const float* db1  = (const float*)d_in[15];
    const float* dg1  = (const float*)d_in[16];
    const float* dbe1 = (const float*)d_in[17];
    const float* dm1  = (const float*)d_in[18];
    const float* dv1  = (const float*)d_in[19];
    const float* dW2  = (const float*)d_in[20];
    const float* db2  = (const float*)d_in[21];
    const float* dg2  = (const float*)d_in[22];
    const float* dbe2 = (const float*)d_in[23];
    const float* dm2  = (const float*)d_in[24];
    const float* dv2  = (const float*)d_in[25];
    const float* gum  = (const float*)d_in[26];

    float* out  = (float*)d_out;
    float* xhat = out;                                  // [MM, DD]
    float* ent  = xhat + (size_t)MM * DD;               // [QN, MM]
    float* lat  = ent  + (size_t)QN * MM;               // [QN, MM, NN]
    float* idxo = lat  + (size_t)QN * MM * NN;          // [QN, MM]
    float* zs   = idxo + (size_t)QN * MM;               // [QN, MM, NN]

    __nv_bfloat16 *Ahi, *Alo, *Hhi, *Hlo, *Wthi, *Wtlo;
    cudaGetSymbolAddress((void**)&Ahi,  g_Ahi);
    cudaGetSymbolAddress((void**)&Alo,  g_Alo);
    cudaGetSymbolAddress((void**)&Hhi,  g_Hhi);
    cudaGetSymbolAddress((void**)&Hlo,  g_Hlo);
    cudaGetSymbolAddress((void**)&Wthi, g_Wthi);
    cudaGetSymbolAddress((void**)&Wtlo, g_Wtlo);

    cudaFuncSetAttribute(mma_gemm, cudaFuncAttributeMaxDynamicSharedMemorySize, SMEM_G);

    init_kernel<<<(MM*DD/4 + 255) / 256, 256>>>(x);
    wsplit_all<<<5888, dim3(32, 8)>>>(pW1, pW2, dW1, dW2);

    for (int i = 0; i < QN; i++) {
        // h = blk(res @ pW1) -> bf16 split [8192 x 512]
        mma_gemm<<<dim3(HH/128, MM/128), 256, SMEM_G>>>(
            Ahi, Alo, Wthi + O_P1 + (size_t)i*SZ_P1, Wtlo + O_P1 + (size_t)i*SZ_P1,
            pb1 + i*HH, pg1 + i*HH, pbe1 + i*HH, pm1 + i*HH, pv1 + i*HH,
            nullptr, Hhi, Hlo, DD, 1);
        // z = blk(h @ pW2) -> fp32 zs slice [8192 x 1024]
        float* z_i = zs + (size_t)i * MM * NN;
        mma_gemm<<<dim3(NN/128, MM/128), 256, SMEM_G>>>(
            Hhi, Hlo, Wthi + O_P2 + (size_t)i*SZ_P2, Wtlo + O_P2 + (size_t)i*SZ_P2,
            pb2 + i*NN, pg2 + i*NN, pbe2 + i*NN, pm2 + i*NN, pv2 + i*NN,
            z_i, nullptr, nullptr, HH, 0);
        token_kernel<<<MM, 256>>>(
            z_i, gum + (size_t)i * MM * NN, cb + (size_t)i * NN * DD, x,
            ent + (size_t)i * MM, lat + (size_t)i * MM * NN, idxo + (size_t)i * MM,
            (i == QN - 1) ? 1 : 0);
    }

    // decoder (Ahi/Alo hold split(qout))
    mma_gemm<<<dim3(DD2/128, MM/128), 256, SMEM_G>>>(
        Ahi, Alo, Wthi + O_D1, Wtlo + O_D1,
        db1, dg1, dbe1, dm1, dv1,
        nullptr, Hhi, Hlo, DD, 1);
    mma_gemm<<<dim3(DD/128, MM/128), 256, SMEM_G>>>(
        Hhi, Hlo, Wthi + O_D2, Wtlo + O_D2,
        db2, dg2, dbe2, dm2, dv2,
        xhat, nullptr, nullptr, DD2, 0);
}

// round 13
// speedup vs baseline: 1.1287x; 1.0779x over previous
#include <cuda_runtime.h>
#include <cuda_bf16.h>
#include <cuda_fp16.h>
#include <math.h>
#include <stdint.h>

#define QN 4
#define DD 768
#define NN 1024
#define HH 512
#define MM 8192
#define DD2 1536

// ---------------- device scratch (no runtime allocation) -------------------
__device__ float g_res[MM*DD];
__device__ __align__(128) unsigned short g_Ahi[MM*DD];
__device__ __align__(128) unsigned short g_Alo[MM*DD];
__device__ __align__(128) unsigned short g_Hhi[MM*DD2];
__device__ __align__(128) unsigned short g_Hlo[MM*DD2];
#define WT_TOTAL 6029312
__device__ __align__(128) unsigned short g_Wthi[WT_TOTAL];
__device__ __align__(128) unsigned short g_Wtlo[WT_TOTAL];

// weight-split layout (elements)
#define O_P1 0
#define SZ_P1 393216            /* 512*768  */
#define O_P2 1572864
#define SZ_P2 524288            /* 1024*512 */
#define O_D1 3670016
#define O_D2 4849664

// ---------------- PTX helpers ----------------------------------------------
__device__ __forceinline__ uint32_t smem_u32(const void* p) {
    uint32_t a;
    asm("{ .reg .u64 t; cvta.to.shared.u64 t, %1; cvt.u32.u64 %0, t; }" : "=r"(a) : "l"(p));
    return a;
}
#define CP_ASYNC16(dst, src) \
    asm volatile("cp.async.cg.shared.global [%0], [%1], 16;\n" :: "r"(dst), "l"(src))
#define CP_COMMIT() asm volatile("cp.async.commit_group;\n" ::: "memory")
#define CP_WAIT(n)  asm volatile("cp.async.wait_group %0;\n" :: "n"(n) : "memory")

#define LDSM4(f, addr) \
    asm volatile("ldmatrix.sync.aligned.m8n8.x4.shared.b16 {%0,%1,%2,%3}, [%4];\n" \
        : "=r"((f)[0]), "=r"((f)[1]), "=r"((f)[2]), "=r"((f)[3]) : "r"(addr))

template<int F2>
__device__ __forceinline__ void mma_d(float* d, const uint32_t* a, uint32_t b0, uint32_t b1) {
    if (F2) {
        asm volatile("mma.sync.aligned.m16n8k16.row.col.f32.f16.f16.f32 "
            "{%0,%1,%2,%3}, {%4,%5,%6,%7}, {%8,%9}, {%0,%1,%2,%3};\n"
            : "+f"(d[0]), "+f"(d[1]), "+f"(d[2]), "+f"(d[3])
            : "r"(a[0]), "r"(a[1]), "r"(a[2]), "r"(a[3]), "r"(b0), "r"(b1));
    } else {
        asm volatile("mma.sync.aligned.m16n8k16.row.col.f32.bf16.bf16.f32 "
            "{%0,%1,%2,%3}, {%4,%5,%6,%7}, {%8,%9}, {%0,%1,%2,%3};\n"
            : "+f"(d[0]), "+f"(d[1]), "+f"(d[2]), "+f"(d[3])
            : "r"(a[0]), "r"(a[1]), "r"(a[2]), "r"(a[3]), "r"(b0), "r"(b1));
    }
}

// ---------------- small kernels --------------------------------------------
// init: res=x, split(x) -> Ahi/Alo (bf16)
__global__ void init_kernel(const float* __restrict__ x) {
    int i = blockIdx.x * blockDim.x + threadIdx.x;
    if (i >= MM*DD/4) return;
    float4 a = ((const float4*)x)[i];
    ((float4*)g_res)[i] = a;
    float av[4] = {a.x, a.y, a.z, a.w};
    unsigned short h[4], l[4];
#pragma unroll
    for (int j = 0; j < 4; j++) {
        __nv_bfloat16 hb = __float2bfloat16(av[j]);
        __nv_bfloat16 lb = __float2bfloat16(av[j] - __bfloat162float(hb));
        h[j] = *(unsigned short*)&hb;
        l[j] = *(unsigned short*)&lb;
    }
    ((ushort4*)g_Ahi)[i] = make_ushort4(h[0], h[1], h[2], h[3]);
    ((ushort4*)g_Alo)[i] = make_ushort4(l[0], l[1], l[2], l[3]);
}

// ALL weight transposes+splits in ONE launch.
// Posterior weights -> bf16 hi/lo split. Decoder weights -> single fp16.
__global__ void wsplit_all(const float* __restrict__ pW1, const float* __restrict__ pW2,
                           const float* __restrict__ dW1, const float* __restrict__ dW2) {
    __shared__ float t[32][33];
    int tb = blockIdx.x;
    const float* W;
    int K, N, f16 = 0;
    size_t dstoff;
    if (tb < 1536) {
        int i = tb / 384; tb -= i * 384;
        W = pW1 + (size_t)i * DD * HH; K = DD; N = HH; dstoff = O_P1 + (size_t)i * SZ_P1;
    } else if (tb < 3584) {
        int u = tb - 1536; int i = u / 512; tb = u - i * 512;
        W = pW2 + (size_t)i * HH * NN; K = HH; N = NN; dstoff = O_P2 + (size_t)i * SZ_P2;
    } else if (tb < 4736) {
        tb -= 3584; W = dW1; K = DD; N = DD2; dstoff = O_D1; f16 = 1;
    } else {
        tb -= 4736; W = dW2; K = DD2; N = DD; dstoff = O_D2; f16 = 1;
    }
    int ntx = N >> 5;
    int n0 = (tb % ntx) << 5, k0 = (tb / ntx) << 5;
    unsigned short* Thi = g_Wthi + dstoff;
    unsigned short* Tlo = g_Wtlo + dstoff;
    for (int i = threadIdx.y; i < 32; i += 8)
        t[i][threadIdx.x] = W[(size_t)(k0 + i) * N + n0 + threadIdx.x];
    __syncthreads();
    for (int i = threadIdx.y; i < 32; i += 8) {
        float val = t[threadIdx.x][i];
        size_t o = (size_t)(n0 + i) * K + k0 + threadIdx.x;
        if (f16) {
            __half hf = __float2half(val);
            Thi[o] = *(unsigned short*)&hf;
        } else {
            __nv_bfloat16 h = __float2bfloat16(val);
            __nv_bfloat16 l = __float2bfloat16(val - __bfloat162float(h));
            Thi[o] = *(unsigned short*)&h;
            Tlo[o] = *(unsigned short*)&l;
        }
    }
}

// ---- templated mma.sync split GEMM (R12 structure) -------------------------
// F2=0: bf16 3-pass (hh + hi*lo + lo*hi), W hi/lo. F2=1: fp16 2-pass
// (Ahi*W + Alo*W), W single (Wlo param ignored; both loader halves read Whi).
// 128x128 CTA tile, BK=64, interleaved 256B rows, 3-stage cp.async, one sync
// per chunk, kk-stagger + fragment double-buffer. 8 warps x (64x32).
// mode 0: fp32 out. mode 1: bf16 hi/lo split out. mode 2: f16 hi/lo split out.
#define GS_STAGE 65536
#define GS_SC    196608
#define SMEM_G   (196608 + 1024)

template<int F2>
__global__ __launch_bounds__(256, 1)
void mma_gemm(const unsigned short* __restrict__ Ahi, const unsigned short* __restrict__ Alo,
              const unsigned short* __restrict__ Whi, const unsigned short* __restrict__ Wlo,
              const float* __restrict__ bb, const float* __restrict__ gg,
              const float* __restrict__ be, const float* __restrict__ mm_,
              const float* __restrict__ vv,
              float* __restrict__ Cf, unsigned short* __restrict__ Chi,
              unsigned short* __restrict__ Clo, int K, int mode)
{
    extern __shared__ __align__(1024) char smem[];
    const uint32_t sbase = smem_u32(smem);
    float* scp = (float*)(smem + GS_SC);
    float* ofp = scp + 128;
    const int tid = threadIdx.x;
    const int Nc = gridDim.x * 128;
    const int n0 = blockIdx.x * 128;
    const int m0 = blockIdx.y * 128;

    if (tid < 128) {
        int c = n0 + tid;
        float s = gg[c] * rsqrtf(vv[c] + 1e-5f);
        scp[tid] = s;
        ofp[tid] = (bb[c] - mm_[c]) * s + be[c];
    }

    const int lane = tid & 31, wid = tid >> 5;
    const int wm = (wid >> 2) << 6;
    const int wn = (wid & 3) << 5;
    const int kst = (wid >> 2) << 1;

    float acc[4][4][4];
#pragma unroll
    for (int im = 0; im < 4; im++)
#pragma unroll
        for (int in = 0; in < 4; in++)
#pragma unroll
            for (int r = 0; r < 4; r++) acc[im][in][r] = 0.f;

    uint32_t aoff[4]; int asw[4];
#pragma unroll
    for (int im = 0; im < 4; im++) {
        int r = wm + (im << 4) + (lane & 15);
        aoff[im] = (uint32_t)(r << 8);
        asw[im] = r & 7;
    }
    const int acb = lane >> 4;
    uint32_t boff[2]; int bsw[2];
#pragma unroll
    for (int jn = 0; jn < 2; jn++) {
        int r = wn + (jn << 4) + (lane & 7) + (((lane >> 4) & 1) << 3);
        boff[jn] = (uint32_t)(r << 8);
        bsw[jn] = r & 7;
    }
    const int bcb = (lane >> 3) & 1;

    const int NC = K >> 6;

    const int lrow0 = tid >> 4;
    const int lc16  = tid & 15;
    const int lhalf = lc16 >> 3;
    const int lcc   = lc16 & 7;
    const unsigned short* Asrc = lhalf ? Alo : Ahi;
    const unsigned short* Wsrc = (F2 || !lhalf) ? Whi : Wlo;
    const uint32_t lhoff = (uint32_t)(lhalf << 7);

    auto load_chunk = [&](int c, int s) {
        int k0 = c << 6;
        uint32_t bA = sbase + s * GS_STAGE;
        uint32_t bB = bA + 32768;
#pragma unroll
        for (int j = 0; j < 8; j++) {
            int row = lrow0 + (j << 4);
            uint32_t sw = (uint32_t)(row << 8) + lhoff + (uint32_t)((lcc ^ (row & 7)) << 4);
            CP_ASYNC16(bA + sw, Asrc + (size_t)(m0 + row) * K + k0 + (lcc << 3));
            CP_ASYNC16(bB + sw, Wsrc + (size_t)(n0 + row) * K + k0 + (lcc << 3));
        }
    };

    load_chunk(0, 0); CP_COMMIT();
    load_chunk(1, 1); CP_COMMIT();

    uint32_t afh[2][4][4], afl[2][4][4], bfh[2][2][4], bfl[2][2][4];

    for (int c = 0; c < NC; c++) {
        CP_WAIT(1);
        __syncthreads();
        if (c + 2 < NC) load_chunk(c + 2, (c + 2) % 3);
        CP_COMMIT();

        uint32_t sA = sbase + (c % 3) * GS_STAGE;
        uint32_t sB = sA + 32768;

        {
            const int kr = kst;
            const int sela = (kr << 1) + acb;
            const int selb = (kr << 1) + bcb;
#pragma unroll
            for (int im = 0; im < 4; im++) {
                uint32_t base = sA + aoff[im] + (uint32_t)((sela ^ asw[im]) << 4);
                LDSM4(afh[0][im], base);
                LDSM4(afl[0][im], base + 128);
            }
#pragma unroll
            for (int jn = 0; jn < 2; jn++) {
                uint32_t base = sB + boff[jn] + (uint32_t)((selb ^ bsw[jn]) << 4);
                LDSM4(bfh[0][jn], base);
                if (!F2) LDSM4(bfl[0][jn], base + 128);
            }
        }

#pragma unroll
        for (int kk = 0; kk < 4; kk++) {
            const int cur = kk & 1;
            const int nxt = cur ^ 1;
            if (kk < 3) {
                const int kr = (kk + 1 + kst) & 3;
                const int sela = (kr << 1) + acb;
                const int selb = (kr << 1) + bcb;
#pragma unroll
                for (int im = 0; im < 4; im++) {
                    uint32_t base = sA + aoff[im] + (uint32_t)((sela ^ asw[im]) << 4);
                    LDSM4(afh[nxt][im], base);
                    LDSM4(afl[nxt][im], base + 128);
                }
#pragma unroll
                for (int jn = 0; jn < 2; jn++) {
                    uint32_t base = sB + boff[jn] + (uint32_t)((selb ^ bsw[jn]) << 4);
                    LDSM4(bfh[nxt][jn], base);
                    if (!F2) LDSM4(bfl[nxt][jn], base + 128);
                }
            }
            // pass 1: Ahi x Whi
#pragma unroll
            for (int im = 0; im < 4; im++)
#pragma unroll
                for (int in = 0; in < 4; in++) {
                    const uint32_t* bp = bfh[cur][in >> 1];
                    if (in & 1) mma_d<F2>(acc[im][in], afh[cur][im], bp[2], bp[3]);
                    else        mma_d<F2>(acc[im][in], afh[cur][im], bp[0], bp[1]);
                }
            // pass 2 (3-pass only): Ahi x Wlo
            if (!F2) {
#pragma unroll
                for (int im = 0; im < 4; im++)
#pragma unroll
                    for (int in = 0; in < 4; in++) {
                        const uint32_t* bp = bfl[cur][in >> 1];
                        if (in & 1) mma_d<F2>(acc[im][in], afh[cur][im], bp[2], bp[3]);
                        else        mma_d<F2>(acc[im][in], afh[cur][im], bp[0], bp[1]);
                    }
            }
            // pass 3: Alo x Whi
#pragma unroll
            for (int im = 0; im < 4; im++)
#pragma unroll
                for (int in = 0; in < 4; in++) {
                    const uint32_t* bp = bfh[cur][in >> 1];
                    if (in & 1) mma_d<F2>(acc[im][in], afl[cur][im], bp[2], bp[3]);
                    else        mma_d<F2>(acc[im][in], afl[cur][im], bp[0], bp[1]);
                }
        }
    }

    // ---- epilogue: BN + ReLU ------------------------------------------------
    const int rbase = m0 + wm + (lane >> 2);
    const int clbase = wn + ((lane & 3) << 1);
#pragma unroll
    for (int im = 0; im < 4; im++) {
#pragma unroll
        for (int in = 0; in < 4; in++) {
            int row = rbase + (im << 4);
            int cl = clbase + (in << 3);
            float s0 = scp[cl], s1 = scp[cl + 1];
            float o0 = ofp[cl], o1 = ofp[cl + 1];
            float v0 = fmaxf(acc[im][in][0] * s0 + o0, 0.f);
            float v1 = fmaxf(acc[im][in][1] * s1 + o1, 0.f);
            float v2 = fmaxf(acc[im][in][2] * s0 + o0, 0.f);
            float v3 = fmaxf(acc[im][in][3] * s1 + o1, 0.f);
            size_t p0 = (size_t)row * Nc + n0 + cl;
            size_t p1 = (size_t)(row + 8) * Nc + n0 + cl;
            if (mode == 0) {
                float2 w0; w0.x = v0; w0.y = v1;
                float2 w1; w1.x = v2; w1.y = v3;
                *(float2*)&Cf[p0] = w0;
                *(float2*)&Cf[p1] = w1;
            } else if (mode == 1) {
                __nv_bfloat16 h0 = __float2bfloat16(v0);
                __nv_bfloat16 h1 = __float2bfloat16(v1);
                __nv_bfloat16 h2 = __float2bfloat16(v2);
                __nv_bfloat16 h3 = __float2bfloat16(v3);
                unsigned short l0b, l1b, l2b, l3b;
                __nv_bfloat16 t0 = __float2bfloat16(v0 - __bfloat162float(h0)); l0b = *(unsigned short*)&t0;
                __nv_bfloat16 t1 = __float2bfloat16(v1 - __bfloat162float(h1)); l1b = *(unsigned short*)&t1;
                __nv_bfloat16 t2 = __float2bfloat16(v2 - __bfloat162float(h2)); l2b = *(unsigned short*)&t2;
                __nv_bfloat16 t3 = __float2bfloat16(v3 - __bfloat162float(h3)); l3b = *(unsigned short*)&t3;
                ushort2 hp0; hp0.x = *(unsigned short*)&h0; hp0.y = *(unsigned short*)&h1;
                ushort2 hp1; hp1.x = *(unsigned short*)&h2; hp1.y = *(unsigned short*)&h3;
                ushort2 lp0; lp0.x = l0b; lp0.y = l1b;
                ushort2 lp1; lp1.x = l2b; lp1.y = l3b;
                *(ushort2*)&Chi[p0] = hp0;
                *(ushort2*)&Chi[p1] = hp1;
                *(ushort2*)&Clo[p0] = lp0;
                *(ushort2*)&Clo[p1] = lp1;
            } else {
                __half h0 = __float2half(v0);
                __half h1 = __float2half(v1);
                __half h2 = __float2half(v2);
                __half h3 = __float2half(v3);
                __half t0 = __float2half(v0 - __half2float(h0));
                __half t1 = __float2half(v1 - __half2float(h1));
                __half t2 = __float2half(v2 - __half2float(h2));
                __half t3 = __float2half(v3 - __half2float(h3));
                ushort2 hp0; hp0.x = *(unsigned short*)&h0; hp0.y = *(unsigned short*)&h1;
                ushort2 hp1; hp1.x = *(unsigned short*)&h2; hp1.y = *(unsigned short*)&h3;
                ushort2 lp0; lp0.x = *(unsigned short*)&t0; lp0.y = *(unsigned short*)&t1;
                ushort2 lp1; lp1.x = *(unsigned short*)&t2; lp1.y = *(unsigned short*)&t3;
                *(ushort2*)&Chi[p0] = hp0;
                *(ushort2*)&Chi[p1] = hp1;
                *(ushort2*)&Clo[p0] = lp0;
                *(ushort2*)&Clo[p1] = lp1;
            }
        }
    }
}

// ---------------- token kernel (float4) --------------------------------------
// split_mode 0: res -= cb[idx]; emit bf16 split(res).
// split_mode 1: r = res - cb[idx]; emit fp16 split(x - r) (= qout, for decoder)
__global__ void token_kernel(const float* __restrict__ z,
                             const float* __restrict__ gum,
                             const float* __restrict__ cb,
                             const float* __restrict__ x,
                             float* __restrict__ ent_out,
                             float* __restrict__ lat_out,
                             float* __restrict__ idx_out,
                             int split_mode)
{
    const int t = blockIdx.x;
    const int tid = threadIdx.x;
    const int lane = tid & 31, wrp = tid >> 5;

    __shared__ float swa[8];
    __shared__ float swb[8];
    __shared__ int   swi[8];

    float4 z4 = ((const float4*)(z + (size_t)t * NN))[tid];
    float4 g4 = ((const float4*)(gum + (size_t)t * NN))[tid];
    float zv[4] = {z4.x, z4.y, z4.z, z4.w};
    float gv[4] = {g4.x, g4.y, g4.z, g4.w};

    float lmax = -INFINITY;
    float amax = -INFINITY;
    int   aidx = 0x7fffffff;
#pragma unroll
    for (int k = 0; k < 4; k++) {
        lmax = fmaxf(lmax, zv[k]);
        float lg = zv[k] + gv[k];
        if (lg > amax) { amax = lg; aidx = (tid << 2) + k; }
    }
#pragma unroll
    for (int o = 16; o > 0; o >>= 1) {
        lmax = fmaxf(lmax, __shfl_xor_sync(0xffffffffu, lmax, o));
        float ov = __shfl_xor_sync(0xffffffffu, amax, o);
        int   oi = __shfl_xor_sync(0xffffffffu, aidx, o);
        if (ov > amax || (ov == amax && oi < aidx)) { amax = ov; aidx = oi; }
    }
    if (lane == 0) { swa[wrp] = lmax; swb[wrp] = amax; swi[wrp] = aidx; }
    __syncthreads();
    float zmax = swa[0];
    float bv = swb[0]; int bi = swi[0];
#pragma unroll
    for (int w = 1; w < 8; w++) {
        zmax = fmaxf(zmax, swa[w]);
        float ov = swb[w]; int oi = swi[w];
        if (ov > bv || (ov == bv && oi < bi)) { bv = ov; bi = oi; }
    }
    const int idx = bi;
    __syncthreads();

    float ex[4];
    float se = 0.f;
#pragma unroll
    for (int k = 0; k < 4; k++) { ex[k] = expf(zv[k] - zmax); se += ex[k]; }
#pragma unroll
    for (int o = 16; o > 0; o >>= 1) se += __shfl_xor_sync(0xffffffffu, se, o);
    if (lane == 0) swa[wrp] = se;
    __syncthreads();
    float tot = 0.f;
#pragma unroll
    for (int w = 0; w < 8; w++) tot += swa[w];
    const float inv = 1.f / tot;

    float entp = 0.f;
    float lt[4];
#pragma unroll
    for (int k = 0; k < 4; k++) {
        float qy = ex[k] * inv;
        entp -= qy * logf(qy + 1e-10f);
        lt[k] = qy * logf(qy * 1024.f + 1e-10f);
    }
    float4 l4; l4.x = lt[0]; l4.y = lt[1]; l4.z = lt[2]; l4.w = lt[3];
    ((float4*)(lat_out + (size_t)t * NN))[tid] = l4;
#pragma unroll
    for (int o = 16; o > 0; o >>= 1) entp += __shfl_xor_sync(0xffffffffu, entp, o);
    __syncthreads();
    if (lane == 0) swb[wrp] = entp;
    __syncthreads();
    if (tid == 0) {
        float e = 0.f;
#pragma unroll
        for (int w = 0; w < 8; w++) e += swb[w];
        ent_out[t] = e;
        idx_out[t] = (float)idx;
    }

    if (tid < DD/4) {
        const float4* cb4 = (const float4*)(cb + (size_t)idx * DD);
        float4* rr4 = (float4*)(g_res + (size_t)t * DD);
        float4 c4 = cb4[tid];
        float4 r4 = rr4[tid];
        r4.x -= c4.x; r4.y -= c4.y; r4.z -= c4.z; r4.w -= c4.w;
        float sv[4];
        unsigned short h[4], l[4];
        if (split_mode) {
            float4 x4 = ((const float4*)(x + (size_t)t * DD))[tid];
            sv[0] = x4.x - r4.x; sv[1] = x4.y - r4.y;
            sv[2] = x4.z - r4.z; sv[3] = x4.w - r4.w;
#pragma unroll
            for (int k = 0; k < 4; k++) {
                __half hh = __float2half(sv[k]);
                __half ll = __float2half(sv[k] - __half2float(hh));
                h[k] = *(unsigned short*)&hh;
                l[k] = *(unsigned short*)&ll;
            }
        } else {
            rr4[tid] = r4;
            sv[0] = r4.x; sv[1] = r4.y; sv[2] = r4.z; sv[3] = r4.w;
#pragma unroll
            for (int k = 0; k < 4; k++) {
                __nv_bfloat16 hh = __float2bfloat16(sv[k]);
                __nv_bfloat16 ll = __float2bfloat16(sv[k] - __bfloat162float(hh));
                h[k] = *(unsigned short*)&hh;
                l[k] = *(unsigned short*)&ll;
            }
        }
        ((ushort4*)(g_Ahi + (size_t)t * DD))[tid] = make_ushort4(h[0], h[1], h[2], h[3]);
        ((ushort4*)(g_Alo + (size_t)t * DD))[tid] = make_ushort4(l[0], l[1], l[2], l[3]);
    }
}

// ---------------- host launch ----------------------------------------------
extern "C" void kernel_launch(void* const* d_in, const int* in_sizes, int n_in,
                              void* d_out, int out_size)
{
    const float* x    = (const float*)d_in[0];
    const float* cb   = (const float*)d_in[1];
    const float* pW1  = (const float*)d_in[2];
    const float* pb1  = (const float*)d_in[3];
    const float* pg1  = (const float*)d_in[4];
    const float* pbe1 = (const float*)d_in[5];
    const float* pm1  = (const float*)d_in[6];
    const float* pv1  = (const float*)d_in[7];
    const float* pW2  = (const float*)d_in[8];
    const float* pb2  = (const float*)d_in[9];
    const float* pg2  = (const float*)d_in[10];
    const float* pbe2 = (const float*)d_in[11];
    const float* pm2  = (const float*)d_in[12];
    const float* pv2  = (const float*)d_in[13];
    const float* dW1  = (const float*)d_in[14];
    const float* db1  = (const float*)d_in[15];
    const float* dg1  = (const float*)d_in[16];
    const float* dbe1 = (const float*)d_in[17];
    const float* dm1  = (const float*)d_in[18];
    const float* dv1  = (const float*)d_in[19];
    const float* dW2  = (const float*)d_in[20];
    const float* db2  = (const float*)d_in[21];
    const float* dg2  = (const float*)d_in[22];
    const float* dbe2 = (const float*)d_in[23];
    const float* dm2  = (const float*)d_in[24];
    const float* dv2  = (const float*)d_in[25];
    const float* gum  = (const float*)d_in[26];

    float* out  = (float*)d_out;
    float* xhat = out;                                  // [MM, DD]
    float* ent  = xhat + (size_t)MM * DD;               // [QN, MM]
    float* lat  = ent  + (size_t)QN * MM;               // [QN, MM, NN]
    float* idxo = lat  + (size_t)QN * MM * NN;          // [QN, MM]
    float* zs   = idxo + (size_t)QN * MM;               // [QN, MM, NN]

    unsigned short *Ahi, *Alo, *Hhi, *Hlo, *Wthi, *Wtlo;
    cudaGetSymbolAddress((void**)&Ahi,  g_Ahi);
    cudaGetSymbolAddress((void**)&Alo,  g_Alo);
    cudaGetSymbolAddress((void**)&Hhi,  g_Hhi);
    cudaGetSymbolAddress((void**)&Hlo,  g_Hlo);
    cudaGetSymbolAddress((void**)&Wthi, g_Wthi);
    cudaGetSymbolAddress((void**)&Wtlo, g_Wtlo);

    cudaFuncSetAttribute(mma_gemm<0>, cudaFuncAttributeMaxDynamicSharedMemorySize, SMEM_G);
    cudaFuncSetAttribute(mma_gemm<1>, cudaFuncAttributeMaxDynamicSharedMemorySize, SMEM_G);

    init_kernel<<<(MM*DD/4 + 255) / 256, 256>>>(x);
    wsplit_all<<<5888, dim3(32, 8)>>>(pW1, pW2, dW1, dW2);

    for (int i = 0; i < QN; i++) {
        // h = blk(res @ pW1) -> bf16 split [8192 x 512]
        mma_gemm<0><<<dim3(HH/128, MM/128), 256, SMEM_G>>>(
            Ahi, Alo, Wthi + O_P1 + (size_t)i*SZ_P1, Wtlo + O_P1 + (size_t)i*SZ_P1,
            pb1 + i*HH, pg1 + i*HH, pbe1 + i*HH, pm1 + i*HH, pv1 + i*HH,
            nullptr, Hhi, Hlo, DD, 1);
        // z = blk(h @ pW2) -> fp32 zs slice [8192 x 1024]
        float* z_i = zs + (size_t)i * MM * NN;
        mma_gemm<0><<<dim3(NN/128, MM/128), 256, SMEM_G>>>(
            Hhi, Hlo, Wthi + O_P2 + (size_t)i*SZ_P2, Wtlo + O_P2 + (size_t)i*SZ_P2,
            pb2 + i*NN, pg2 + i*NN, pbe2 + i*NN, pm2 + i*NN, pv2 + i*NN,
            z_i, nullptr, nullptr, HH, 0);
        token_kernel<<<MM, 256>>>(
            z_i, gum + (size_t)i * MM * NN, cb + (size_t)i * NN * DD, x,
            ent + (size_t)i * MM, lat + (size_t)i * MM * NN, idxo + (size_t)i * MM,
            (i == QN - 1) ? 1 : 0);
    }

    // decoder: fp16 2-pass (Ahi/Alo hold fp16 split(qout))
    mma_gemm<1><<<dim3(DD2/128, MM/128), 256, SMEM_G>>>(
        Ahi, Alo, Wthi + O_D1, Wthi + O_D1,
        db1, dg1, dbe1, dm1, dv1,
        nullptr, Hhi, Hlo, DD, 2);
    mma_gemm<1><<<dim3(DD/128, MM/128), 256, SMEM_G>>>(
        Hhi, Hlo, Wthi + O_D2, Wthi + O_D2,
        db2, dg2, dbe2, dm2, dv2,
        xhat, nullptr, nullptr, DD2, 0);
}

// round 14
// speedup vs baseline: 1.2328x; 1.0923x over previous
#include <cuda_runtime.h>
#include <cuda_bf16.h>
#include <cuda_fp16.h>
#include <math.h>
#include <stdint.h>

#define QN 4
#define DD 768
#define NN 1024
#define HH 512
#define MM 8192
#define DD2 1536

// ---------------- device scratch (no runtime allocation) -------------------
__device__ float g_res[MM*DD];
__device__ __align__(128) unsigned short g_Ahi[MM*DD];
__device__ __align__(128) unsigned short g_Alo[MM*DD];
__device__ __align__(128) unsigned short g_Hhi[MM*DD2];
__device__ __align__(128) unsigned short g_Hlo[MM*DD2];
#define WT_TOTAL 6029312
__device__ __align__(128) unsigned short g_Wthi[WT_TOTAL];
__device__ __align__(128) unsigned short g_Wtlo[WT_TOTAL];

// weight-split layout (elements)
#define O_P1 0
#define SZ_P1 393216            /* 512*768  */
#define O_P2 1572864
#define SZ_P2 524288            /* 1024*512 */
#define O_D1 3670016
#define O_D2 4849664

// ---------------- PTX helpers ----------------------------------------------
__device__ __forceinline__ uint32_t smem_u32(const void* p) {
    uint32_t a;
    asm("{ .reg .u64 t; cvta.to.shared.u64 t, %1; cvt.u32.u64 %0, t; }" : "=r"(a) : "l"(p));
    return a;
}
#define CP_ASYNC16(dst, src) \
    asm volatile("cp.async.cg.shared.global [%0], [%1], 16;\n" :: "r"(dst), "l"(src))
#define CP_COMMIT() asm volatile("cp.async.commit_group;\n" ::: "memory")
#define CP_WAIT(n)  asm volatile("cp.async.wait_group %0;\n" :: "n"(n) : "memory")

#define LDSM4(f, addr) \
    asm volatile("ldmatrix.sync.aligned.m8n8.x4.shared.b16 {%0,%1,%2,%3}, [%4];\n" \
        : "=r"((f)[0]), "=r"((f)[1]), "=r"((f)[2]), "=r"((f)[3]) : "r"(addr))

// FP16MMA: 1 = f16 inputs, 0 = bf16 inputs (fp32 accumulate both)
template<int FP16MMA>
__device__ __forceinline__ void mma_d(float* d, const uint32_t* a, uint32_t b0, uint32_t b1) {
    if (FP16MMA) {
        asm volatile("mma.sync.aligned.m16n8k16.row.col.f32.f16.f16.f32 "
            "{%0,%1,%2,%3}, {%4,%5,%6,%7}, {%8,%9}, {%0,%1,%2,%3};\n"
            : "+f"(d[0]), "+f"(d[1]), "+f"(d[2]), "+f"(d[3])
            : "r"(a[0]), "r"(a[1]), "r"(a[2]), "r"(a[3]), "r"(b0), "r"(b1));
    } else {
        asm volatile("mma.sync.aligned.m16n8k16.row.col.f32.bf16.bf16.f32 "
            "{%0,%1,%2,%3}, {%4,%5,%6,%7}, {%8,%9}, {%0,%1,%2,%3};\n"
            : "+f"(d[0]), "+f"(d[1]), "+f"(d[2]), "+f"(d[3])
            : "r"(a[0]), "r"(a[1]), "r"(a[2]), "r"(a[3]), "r"(b0), "r"(b1));
    }
}

// ---------------- small kernels --------------------------------------------
// init: res=x, split(x) -> Ahi/Alo (bf16)
__global__ void init_kernel(const float* __restrict__ x) {
    int i = blockIdx.x * blockDim.x + threadIdx.x;
    if (i >= MM*DD/4) return;
    float4 a = ((const float4*)x)[i];
    ((float4*)g_res)[i] = a;
    float av[4] = {a.x, a.y, a.z, a.w};
    unsigned short h[4], l[4];
#pragma unroll
    for (int j = 0; j < 4; j++) {
        __nv_bfloat16 hb = __float2bfloat16(av[j]);
        __nv_bfloat16 lb = __float2bfloat16(av[j] - __bfloat162float(hb));
        h[j] = *(unsigned short*)&hb;
        l[j] = *(unsigned short*)&lb;
    }
    ((ushort4*)g_Ahi)[i] = make_ushort4(h[0], h[1], h[2], h[3]);
    ((ushort4*)g_Alo)[i] = make_ushort4(l[0], l[1], l[2], l[3]);
}

// ALL weight transposes+splits in ONE launch.
// Posterior weights -> bf16 hi/lo split. Decoder weights -> single fp16.
__global__ void wsplit_all(const float* __restrict__ pW1, const float* __restrict__ pW2,
                           const float* __restrict__ dW1, const float* __restrict__ dW2) {
    __shared__ float t[32][33];
    int tb = blockIdx.x;
    const float* W;
    int K, N, f16 = 0;
    size_t dstoff;
    if (tb < 1536) {
        int i = tb / 384; tb -= i * 384;
        W = pW1 + (size_t)i * DD * HH; K = DD; N = HH; dstoff = O_P1 + (size_t)i * SZ_P1;
    } else if (tb < 3584) {
        int u = tb - 1536; int i = u / 512; tb = u - i * 512;
        W = pW2 + (size_t)i * HH * NN; K = HH; N = NN; dstoff = O_P2 + (size_t)i * SZ_P2;
    } else if (tb < 4736) {
        tb -= 3584; W = dW1; K = DD; N = DD2; dstoff = O_D1; f16 = 1;
    } else {
        tb -= 4736; W = dW2; K = DD2; N = DD; dstoff = O_D2; f16 = 1;
    }
    int ntx = N >> 5;
    int n0 = (tb % ntx) << 5, k0 = (tb / ntx) << 5;
    unsigned short* Thi = g_Wthi + dstoff;
    unsigned short* Tlo = g_Wtlo + dstoff;
    for (int i = threadIdx.y; i < 32; i += 8)
        t[i][threadIdx.x] = W[(size_t)(k0 + i) * N + n0 + threadIdx.x];
    __syncthreads();
    for (int i = threadIdx.y; i < 32; i += 8) {
        float val = t[threadIdx.x][i];
        size_t o = (size_t)(n0 + i) * K + k0 + threadIdx.x;
        if (f16) {
            __half hf = __float2half(val);
            Thi[o] = *(unsigned short*)&hf;
        } else {
            __nv_bfloat16 h = __float2bfloat16(val);
            __nv_bfloat16 l = __float2bfloat16(val - __bfloat162float(h));
            Thi[o] = *(unsigned short*)&h;
            Tlo[o] = *(unsigned short*)&l;
        }
    }
}

// ---- templated mma.sync GEMM ------------------------------------------------
// PASSES=3: bf16, hh + Ahi*Wlo + Alo*Whi (posterior; argmax-safe).
// PASSES=1: fp16, single pass Ahi*Whi (decoder; pass Alo=Ahi, Wlo=Whi).
// 128x128 CTA tile, BK=64, interleaved 256B rows ([hi|lo]), 3-stage cp.async,
// one sync/chunk, kk-stagger + frag double-buffer. 8 warps x (64x32).
// mode 0: fp32 out. mode 1: bf16 hi/lo split out. mode 3: single fp16 out.
#define GS_STAGE 65536
#define GS_SC    196608
#define SMEM_G   (196608 + 1024)

template<int PASSES>
__global__ __launch_bounds__(256, 1)
void mma_gemm(const unsigned short* __restrict__ Ahi, const unsigned short* __restrict__ Alo,
              const unsigned short* __restrict__ Whi, const unsigned short* __restrict__ Wlo,
              const float* __restrict__ bb, const float* __restrict__ gg,
              const float* __restrict__ be, const float* __restrict__ mm_,
              const float* __restrict__ vv,
              float* __restrict__ Cf, unsigned short* __restrict__ Chi,
              unsigned short* __restrict__ Clo, int K, int mode)
{
    constexpr int FP16MMA = (PASSES < 3);
    extern __shared__ __align__(1024) char smem[];
    const uint32_t sbase = smem_u32(smem);
    float* scp = (float*)(smem + GS_SC);
    float* ofp = scp + 128;
    const int tid = threadIdx.x;
    const int Nc = gridDim.x * 128;
    const int n0 = blockIdx.x * 128;
    const int m0 = blockIdx.y * 128;

    if (tid < 128) {
        int c = n0 + tid;
        float s = gg[c] * rsqrtf(vv[c] + 1e-5f);
        scp[tid] = s;
        ofp[tid] = (bb[c] - mm_[c]) * s + be[c];
    }

    const int lane = tid & 31, wid = tid >> 5;
    const int wm = (wid >> 2) << 6;
    const int wn = (wid & 3) << 5;
    const int kst = (wid >> 2) << 1;

    float acc[4][4][4];
#pragma unroll
    for (int im = 0; im < 4; im++)
#pragma unroll
        for (int in = 0; in < 4; in++)
#pragma unroll
            for (int r = 0; r < 4; r++) acc[im][in][r] = 0.f;

    uint32_t aoff[4]; int asw[4];
#pragma unroll
    for (int im = 0; im < 4; im++) {
        int r = wm + (im << 4) + (lane & 15);
        aoff[im] = (uint32_t)(r << 8);
        asw[im] = r & 7;
    }
    const int acb = lane >> 4;
    uint32_t boff[2]; int bsw[2];
#pragma unroll
    for (int jn = 0; jn < 2; jn++) {
        int r = wn + (jn << 4) + (lane & 7) + (((lane >> 4) & 1) << 3);
        boff[jn] = (uint32_t)(r << 8);
        bsw[jn] = r & 7;
    }
    const int bcb = (lane >> 3) & 1;

    const int NC = K >> 6;

    const int lrow0 = tid >> 4;
    const int lc16  = tid & 15;
    const int lhalf = lc16 >> 3;
    const int lcc   = lc16 & 7;
    const unsigned short* Asrc = lhalf ? Alo : Ahi;
    const unsigned short* Wsrc = lhalf ? Wlo : Whi;
    const uint32_t lhoff = (uint32_t)(lhalf << 7);

    auto load_chunk = [&](int c, int s) {
        int k0 = c << 6;
        uint32_t bA = sbase + s * GS_STAGE;
        uint32_t bB = bA + 32768;
#pragma unroll
        for (int j = 0; j < 8; j++) {
            int row = lrow0 + (j << 4);
            uint32_t sw = (uint32_t)(row << 8) + lhoff + (uint32_t)((lcc ^ (row & 7)) << 4);
            CP_ASYNC16(bA + sw, Asrc + (size_t)(m0 + row) * K + k0 + (lcc << 3));
            CP_ASYNC16(bB + sw, Wsrc + (size_t)(n0 + row) * K + k0 + (lcc << 3));
        }
    };

    load_chunk(0, 0); CP_COMMIT();
    load_chunk(1, 1); CP_COMMIT();

    uint32_t afh[2][4][4], afl[2][4][4], bfh[2][2][4], bfl[2][2][4];

    for (int c = 0; c < NC; c++) {
        CP_WAIT(1);
        __syncthreads();
        if (c + 2 < NC) load_chunk(c + 2, (c + 2) % 3);
        CP_COMMIT();

        uint32_t sA = sbase + (c % 3) * GS_STAGE;
        uint32_t sB = sA + 32768;

        {
            const int kr = kst;
            const int sela = (kr << 1) + acb;
            const int selb = (kr << 1) + bcb;
#pragma unroll
            for (int im = 0; im < 4; im++) {
                uint32_t base = sA + aoff[im] + (uint32_t)((sela ^ asw[im]) << 4);
                LDSM4(afh[0][im], base);
                if (PASSES >= 2) LDSM4(afl[0][im], base + 128);
            }
#pragma unroll
            for (int jn = 0; jn < 2; jn++) {
                uint32_t base = sB + boff[jn] + (uint32_t)((selb ^ bsw[jn]) << 4);
                LDSM4(bfh[0][jn], base);
                if (PASSES == 3) LDSM4(bfl[0][jn], base + 128);
            }
        }

#pragma unroll
        for (int kk = 0; kk < 4; kk++) {
            const int cur = kk & 1;
            const int nxt = cur ^ 1;
            if (kk < 3) {
                const int kr = (kk + 1 + kst) & 3;
                const int sela = (kr << 1) + acb;
                const int selb = (kr << 1) + bcb;
#pragma unroll
                for (int im = 0; im < 4; im++) {
                    uint32_t base = sA + aoff[im] + (uint32_t)((sela ^ asw[im]) << 4);
                    LDSM4(afh[nxt][im], base);
                    if (PASSES >= 2) LDSM4(afl[nxt][im], base + 128);
                }
#pragma unroll
                for (int jn = 0; jn < 2; jn++) {
                    uint32_t base = sB + boff[jn] + (uint32_t)((selb ^ bsw[jn]) << 4);
                    LDSM4(bfh[nxt][jn], base);
                    if (PASSES == 3) LDSM4(bfl[nxt][jn], base + 128);
                }
            }
            // pass 1: Ahi x Whi
#pragma unroll
            for (int im = 0; im < 4; im++)
#pragma unroll
                for (int in = 0; in < 4; in++) {
                    const uint32_t* bp = bfh[cur][in >> 1];
                    if (in & 1) mma_d<FP16MMA>(acc[im][in], afh[cur][im], bp[2], bp[3]);
                    else        mma_d<FP16MMA>(acc[im][in], afh[cur][im], bp[0], bp[1]);
                }
            // pass 2: Ahi x Wlo
            if (PASSES == 3) {
#pragma unroll
                for (int im = 0; im < 4; im++)
#pragma unroll
                    for (int in = 0; in < 4; in++) {
                        const uint32_t* bp = bfl[cur][in >> 1];
                        if (in & 1) mma_d<FP16MMA>(acc[im][in], afh[cur][im], bp[2], bp[3]);
                        else        mma_d<FP16MMA>(acc[im][in], afh[cur][im], bp[0], bp[1]);
                    }
            }
            // pass 3: Alo x Whi
            if (PASSES >= 2) {
#pragma unroll
                for (int im = 0; im < 4; im++)
#pragma unroll
                    for (int in = 0; in < 4; in++) {
                        const uint32_t* bp = bfh[cur][in >> 1];
                        if (in & 1) mma_d<FP16MMA>(acc[im][in], afl[cur][im], bp[2], bp[3]);
                        else        mma_d<FP16MMA>(acc[im][in], afl[cur][im], bp[0], bp[1]);
                    }
            }
        }
    }

    // ---- epilogue: BN + ReLU ------------------------------------------------
    const int rbase = m0 + wm + (lane >> 2);
    const int clbase = wn + ((lane & 3) << 1);
#pragma unroll
    for (int im = 0; im < 4; im++) {
#pragma unroll
        for (int in = 0; in < 4; in++) {
            int row = rbase + (im << 4);
            int cl = clbase + (in << 3);
            float s0 = scp[cl], s1 = scp[cl + 1];
            float o0 = ofp[cl], o1 = ofp[cl + 1];
            float v0 = fmaxf(acc[im][in][0] * s0 + o0, 0.f);
            float v1 = fmaxf(acc[im][in][1] * s1 + o1, 0.f);
            float v2 = fmaxf(acc[im][in][2] * s0 + o0, 0.f);
            float v3 = fmaxf(acc[im][in][3] * s1 + o1, 0.f);
            size_t p0 = (size_t)row * Nc + n0 + cl;
            size_t p1 = (size_t)(row + 8) * Nc + n0 + cl;
            if (mode == 0) {
                float2 w0; w0.x = v0; w0.y = v1;
                float2 w1; w1.x = v2; w1.y = v3;
                *(float2*)&Cf[p0] = w0;
                *(float2*)&Cf[p1] = w1;
            } else if (mode == 1) {
                __nv_bfloat16 h0 = __float2bfloat16(v0);
                __nv_bfloat16 h1 = __float2bfloat16(v1);
                __nv_bfloat16 h2 = __float2bfloat16(v2);
                __nv_bfloat16 h3 = __float2bfloat16(v3);
                __nv_bfloat16 t0 = __float2bfloat16(v0 - __bfloat162float(h0));
                __nv_bfloat16 t1 = __float2bfloat16(v1 - __bfloat162float(h1));
                __nv_bfloat16 t2 = __float2bfloat16(v2 - __bfloat162float(h2));
                __nv_bfloat16 t3 = __float2bfloat16(v3 - __bfloat162float(h3));
                ushort2 hp0; hp0.x = *(unsigned short*)&h0; hp0.y = *(unsigned short*)&h1;
                ushort2 hp1; hp1.x = *(unsigned short*)&h2; hp1.y = *(unsigned short*)&h3;
                ushort2 lp0; lp0.x = *(unsigned short*)&t0; lp0.y = *(unsigned short*)&t1;
                ushort2 lp1; lp1.x = *(unsigned short*)&t2; lp1.y = *(unsigned short*)&t3;
                *(ushort2*)&Chi[p0] = hp0;
                *(ushort2*)&Chi[p1] = hp1;
                *(ushort2*)&Clo[p0] = lp0;
                *(ushort2*)&Clo[p1] = lp1;
            } else {
                __half h0 = __float2half(v0);
                __half h1 = __float2half(v1);
                __half h2 = __float2half(v2);
                __half h3 = __float2half(v3);
                ushort2 hp0; hp0.x = *(unsigned short*)&h0; hp0.y = *(unsigned short*)&h1;
                ushort2 hp1; hp1.x = *(unsigned short*)&h2; hp1.y = *(unsigned short*)&h3;
                *(ushort2*)&Chi[p0] = hp0;
                *(ushort2*)&Chi[p1] = hp1;
            }
        }
    }
}

// ---------------- token kernel (float4) --------------------------------------
// split_mode 0: res -= cb[idx]; emit bf16 split(res) -> g_Ahi/g_Alo.
// split_mode 1: r = res - cb[idx]; emit SINGLE fp16 (x - r) (= qout) -> g_Ahi.
__global__ void token_kernel(const float* __restrict__ z,
                             const float* __restrict__ gum,
                             const float* __restrict__ cb,
                             const float* __restrict__ x,
                             float* __restrict__ ent_out,
                             float* __restrict__ lat_out,
                             float* __restrict__ idx_out,
                             int split_mode)
{
    const int t = blockIdx.x;
    const int tid = threadIdx.x;
    const int lane = tid & 31, wrp = tid >> 5;

    __shared__ float swa[8];
    __shared__ float swb[8];
    __shared__ int   swi[8];

    float4 z4 = ((const float4*)(z + (size_t)t * NN))[tid];
    float4 g4 = ((const float4*)(gum + (size_t)t * NN))[tid];
    float zv[4] = {z4.x, z4.y, z4.z, z4.w};
    float gv[4] = {g4.x, g4.y, g4.z, g4.w};

    float lmax = -INFINITY;
    float amax = -INFINITY;
    int   aidx = 0x7fffffff;
#pragma unroll
    for (int k = 0; k < 4; k++) {
        lmax = fmaxf(lmax, zv[k]);
        float lg = zv[k] + gv[k];
        if (lg > amax) { amax = lg; aidx = (tid << 2) + k; }
    }
#pragma unroll
    for (int o = 16; o > 0; o >>= 1) {
        lmax = fmaxf(lmax, __shfl_xor_sync(0xffffffffu, lmax, o));
        float ov = __shfl_xor_sync(0xffffffffu, amax, o);
        int   oi = __shfl_xor_sync(0xffffffffu, aidx, o);
        if (ov > amax || (ov == amax && oi < aidx)) { amax = ov; aidx = oi; }
    }
    if (lane == 0) { swa[wrp] = lmax; swb[wrp] = amax; swi[wrp] = aidx; }
    __syncthreads();
    float zmax = swa[0];
    float bv = swb[0]; int bi = swi[0];
#pragma unroll
    for (int w = 1; w < 8; w++) {
        zmax = fmaxf(zmax, swa[w]);
        float ov = swb[w]; int oi = swi[w];
        if (ov > bv || (ov == bv && oi < bi)) { bv = ov; bi = oi; }
    }
    const int idx = bi;
    __syncthreads();

    float ex[4];
    float se = 0.f;
#pragma unroll
    for (int k = 0; k < 4; k++) { ex[k] = expf(zv[k] - zmax); se += ex[k]; }
#pragma unroll
    for (int o = 16; o > 0; o >>= 1) se += __shfl_xor_sync(0xffffffffu, se, o);
    if (lane == 0) swa[wrp] = se;
    __syncthreads();
    float tot = 0.f;
#pragma unroll
    for (int w = 0; w < 8; w++) tot += swa[w];
    const float inv = 1.f / tot;

    float entp = 0.f;
    float lt[4];
#pragma unroll
    for (int k = 0; k < 4; k++) {
        float qy = ex[k] * inv;
        entp -= qy * logf(qy + 1e-10f);
        lt[k] = qy * logf(qy * 1024.f + 1e-10f);
    }
    float4 l4; l4.x = lt[0]; l4.y = lt[1]; l4.z = lt[2]; l4.w = lt[3];
    ((float4*)(lat_out + (size_t)t * NN))[tid] = l4;
#pragma unroll
    for (int o = 16; o > 0; o >>= 1) entp += __shfl_xor_sync(0xffffffffu, entp, o);
    __syncthreads();
    if (lane == 0) swb[wrp] = entp;
    __syncthreads();
    if (tid == 0) {
        float e = 0.f;
#pragma unroll
        for (int w = 0; w < 8; w++) e += swb[w];
        ent_out[t] = e;
        idx_out[t] = (float)idx;
    }

    if (tid < DD/4) {
        const float4* cb4 = (const float4*)(cb + (size_t)idx * DD);
        float4* rr4 = (float4*)(g_res + (size_t)t * DD);
        float4 c4 = cb4[tid];
        float4 r4 = rr4[tid];
        r4.x -= c4.x; r4.y -= c4.y; r4.z -= c4.z; r4.w -= c4.w;
        if (split_mode) {
            float4 x4 = ((const float4*)(x + (size_t)t * DD))[tid];
            float sv[4] = {x4.x - r4.x, x4.y - r4.y, x4.z - r4.z, x4.w - r4.w};
            unsigned short h[4];
#pragma unroll
            for (int k = 0; k < 4; k++) {
                __half hh = __float2half(sv[k]);
                h[k] = *(unsigned short*)&hh;
            }
            ((ushort4*)(g_Ahi + (size_t)t * DD))[tid] = make_ushort4(h[0], h[1], h[2], h[3]);
        } else {
            rr4[tid] = r4;
            float sv[4] = {r4.x, r4.y, r4.z, r4.w};
            unsigned short h[4], l[4];
#pragma unroll
            for (int k = 0; k < 4; k++) {
                __nv_bfloat16 hh = __float2bfloat16(sv[k]);
                __nv_bfloat16 ll = __float2bfloat16(sv[k] - __bfloat162float(hh));
                h[k] = *(unsigned short*)&hh;
                l[k] = *(unsigned short*)&ll;
            }
            ((ushort4*)(g_Ahi + (size_t)t * DD))[tid] = make_ushort4(h[0], h[1], h[2], h[3]);
            ((ushort4*)(g_Alo + (size_t)t * DD))[tid] = make_ushort4(l[0], l[1], l[2], l[3]);
        }
    }
}

// ---------------- host launch ----------------------------------------------
extern "C" void kernel_launch(void* const* d_in, const int* in_sizes, int n_in,
                              void* d_out, int out_size)
{
    const float* x    = (const float*)d_in[0];
    const float* cb   = (const float*)d_in[1];
    const float* pW1  = (const float*)d_in[2];
    const float* pb1  = (const float*)d_in[3];
    const float* pg1  = (const float*)d_in[4];
    const float* pbe1 = (const float*)d_in[5];
    const float* pm1  = (const float*)d_in[6];
    const float* pv1  = (const float*)d_in[7];
    const float* pW2  = (const float*)d_in[8];
    const float* pb2  = (const float*)d_in[9];
    const float* pg2  = (const float*)d_in[10];
    const float* pbe2 = (const float*)d_in[11];
    const float* pm2  = (const float*)d_in[12];
    const float* pv2  = (const float*)d_in[13];
    const float* dW1  = (const float*)d_in[14];
    const float* db1  = (const float*)d_in[15];
    const float* dg1  = (const float*)d_in[16];
    const float* dbe1 = (const float*)d_in[17];
    const float* dm1  = (const float*)d_in[18];
    const float* dv1  = (const float*)d_in[19];
    const float* dW2  = (const float*)d_in[20];
    const float* db2  = (const float*)d_in[21];
    const float* dg2  = (const float*)d_in[22];
    const float* dbe2 = (const float*)d_in[23];
    const float* dm2  = (const float*)d_in[24];
    const float* dv2  = (const float*)d_in[25];
    const float* gum  = (const float*)d_in[26];

    float* out  = (float*)d_out;
    float* xhat = out;                                  // [MM, DD]
    float* ent  = xhat + (size_t)MM * DD;               // [QN, MM]
    float* lat  = ent  + (size_t)QN * MM;               // [QN, MM, NN]
    float* idxo = lat  + (size_t)QN * MM * NN;          // [QN, MM]
    float* zs   = idxo + (size_t)QN * MM;               // [QN, MM, NN]

    unsigned short *Ahi, *Alo, *Hhi, *Hlo, *Wthi, *Wtlo;
    cudaGetSymbolAddress((void**)&Ahi,  g_Ahi);
    cudaGetSymbolAddress((void**)&Alo,  g_Alo);
    cudaGetSymbolAddress((void**)&Hhi,  g_Hhi);
    cudaGetSymbolAddress((void**)&Hlo,  g_Hlo);
    cudaGetSymbolAddress((void**)&Wthi, g_Wthi);
    cudaGetSymbolAddress((void**)&Wtlo, g_Wtlo);

    cudaFuncSetAttribute(mma_gemm<3>, cudaFuncAttributeMaxDynamicSharedMemorySize, SMEM_G);
    cudaFuncSetAttribute(mma_gemm<1>, cudaFuncAttributeMaxDynamicSharedMemorySize, SMEM_G);

    init_kernel<<<(MM*DD/4 + 255) / 256, 256>>>(x);
    wsplit_all<<<5888, dim3(32, 8)>>>(pW1, pW2, dW1, dW2);

    for (int i = 0; i < QN; i++) {
        // h = blk(res @ pW1) -> bf16 split [8192 x 512]
        mma_gemm<3><<<dim3(HH/128, MM/128), 256, SMEM_G>>>(
            Ahi, Alo, Wthi + O_P1 + (size_t)i*SZ_P1, Wtlo + O_P1 + (size_t)i*SZ_P1,
            pb1 + i*HH, pg1 + i*HH, pbe1 + i*HH, pm1 + i*HH, pv1 + i*HH,
            nullptr, Hhi, Hlo, DD, 1);
        // z = blk(h @ pW2) -> fp32 zs slice [8192 x 1024]
        float* z_i = zs + (size_t)i * MM * NN;
        mma_gemm<3><<<dim3(NN/128, MM/128), 256, SMEM_G>>>(
            Hhi, Hlo, Wthi + O_P2 + (size_t)i*SZ_P2, Wtlo + O_P2 + (size_t)i*SZ_P2,
            pb2 + i*NN, pg2 + i*NN, pbe2 + i*NN, pm2 + i*NN, pv2 + i*NN,
            z_i, nullptr, nullptr, HH, 0);
        token_kernel<<<MM, 256>>>(
            z_i, gum + (size_t)i * MM * NN, cb + (size_t)i * NN * DD, x,
            ent + (size_t)i * MM, lat + (size_t)i * MM * NN, idxo + (size_t)i * MM,
            (i == QN - 1) ? 1 : 0);
    }

    // decoder: fp16 1-pass (Ahi holds fp16 qout; duplicate ptrs for unused lo)
    mma_gemm<1><<<dim3(DD2/128, MM/128), 256, SMEM_G>>>(
        Ahi, Ahi, Wthi + O_D1, Wthi + O_D1,
        db1, dg1, dbe1, dm1, dv1,
        nullptr, Hhi, nullptr, DD, 3);
    mma_gemm<1><<<dim3(DD/128, MM/128), 256, SMEM_G>>>(
        Hhi, Hhi, Wthi + O_D2, Wthi + O_D2,
        db2, dg2, dbe2, dm2, dv2,
        xhat, nullptr, nullptr, DD2, 0);
}